// round 2
// baseline (speedup 1.0000x reference)
#include <cuda_runtime.h>
#include <math.h>

#define BB 8
#define NN 64
#define HH 512
#define NHEADS 8
#define SPD 64
#define NLAYERS 4
#define FFD 2048

__device__ __constant__ float c_dummy; // nothing

static __device__ __forceinline__ float warpReduceSum(float v) {
    #pragma unroll
    for (int o = 16; o > 0; o >>= 1) v += __shfl_xor_sync(0xffffffffu, v, o);
    return v;
}

// ---------------- scratch (device globals; no allocation) ----------------
__device__ float g_x[BB * NN * HH];
__device__ float g_xn[BB * NN * HH];
__device__ float g_q[BB * NN * HH];
__device__ float g_k[BB * NN * HH];
__device__ float g_v[BB * NN * HH];
__device__ float g_o[BB * NN * HH];
__device__ float g_resid[BB * NN * HH];
__device__ float g_h1[BB * NN * HH];
__device__ float g_ff[BB * NN * FFD];
__device__ float g_bond[(size_t)BB * NN * NN * HH];
__device__ float g_ew[(size_t)BB * NN * NN * HH];

// ---------------- embeddings ----------------
__global__ void embed_x_kernel(const int* __restrict__ ib, const float* __restrict__ emb,
                               float* __restrict__ x) {
    int idx = blockIdx.x * blockDim.x + threadIdx.x;
    if (idx < BB * NN * HH) {
        int row = idx / HH;
        int h = idx - row * HH;
        x[idx] = emb[ib[row] * HH + h];
    }
}

__global__ void embed_bond_kernel(const int* __restrict__ adj, const float* __restrict__ emb,
                                  float* __restrict__ bond) {
    int idx = blockIdx.x * blockDim.x + threadIdx.x; // up to 16,777,216 fits int
    int row = idx / HH;
    int h = idx - row * HH;
    bond[idx] = emb[adj[row] * HH + h];
}

// ---------------- LayerNorm (gamma=1, beta=0) ----------------
__global__ void ln_kernel(const float* __restrict__ in, float* __restrict__ out) {
    __shared__ float sh[8];
    int row = blockIdx.x;
    int t = threadIdx.x; // 256
    const float* r = in + row * HH;
    float v0 = r[t], v1 = r[t + 256];
    int lane = t & 31, w = t >> 5;

    float s = warpReduceSum(v0 + v1);
    if (lane == 0) sh[w] = s;
    __syncthreads();
    float tot = 0.f;
    if (w == 0) {
        float x = (lane < 8) ? sh[lane] : 0.f;
        x = warpReduceSum(x);
        if (lane == 0) sh[0] = x;
    }
    __syncthreads();
    tot = sh[0];
    __syncthreads();
    float mean = tot * (1.f / HH);
    float d0 = v0 - mean, d1 = v1 - mean;

    float vs = warpReduceSum(d0 * d0 + d1 * d1);
    if (lane == 0) sh[w] = vs;
    __syncthreads();
    if (w == 0) {
        float x = (lane < 8) ? sh[lane] : 0.f;
        x = warpReduceSum(x);
        if (lane == 0) sh[0] = x;
    }
    __syncthreads();
    float var = sh[0] * (1.f / HH);
    float rinv = rsqrtf(var + 1e-5f);
    out[row * HH + t] = d0 * rinv;
    out[row * HH + t + 256] = d1 * rinv;
}

// ---------------- generic tiled SGEMM: C = A[M,K] @ B[K,N] (+D / relu) ----------------
// mode 0: C = AB ; mode 1: C = AB + D ; mode 2: C = relu(AB)
#define GBM 64
#define GBN 64
#define GBK 16
__global__ __launch_bounds__(256) void gemm_kernel(const float* __restrict__ A,
                                                   const float* __restrict__ B,
                                                   const float* __restrict__ D,
                                                   float* __restrict__ C,
                                                   int M, int N, int K, int mode) {
    __shared__ float As[GBK][GBM];
    __shared__ float Bs[GBK][GBN];
    int tid = threadIdx.x;
    int tx = tid & 15, ty = tid >> 4;
    int rowBase = blockIdx.y * GBM;
    int colBase = blockIdx.x * GBN;

    float acc[4][4];
    #pragma unroll
    for (int i = 0; i < 4; i++)
        #pragma unroll
        for (int j = 0; j < 4; j++) acc[i][j] = 0.f;

    for (int k0 = 0; k0 < K; k0 += GBK) {
        #pragma unroll
        for (int r = 0; r < 4; r++) {
            int idx = tid + r * 256;
            int m = idx >> 4;       // /16
            int kk = idx & 15;
            As[kk][m] = A[(size_t)(rowBase + m) * K + k0 + kk];
        }
        #pragma unroll
        for (int r = 0; r < 4; r++) {
            int idx = tid + r * 256;
            int kk = idx >> 6;      // /64
            int n = idx & 63;
            Bs[kk][n] = B[(size_t)(k0 + kk) * N + colBase + n];
        }
        __syncthreads();
        #pragma unroll
        for (int kk = 0; kk < GBK; kk++) {
            float a0 = As[kk][ty * 4 + 0];
            float a1 = As[kk][ty * 4 + 1];
            float a2 = As[kk][ty * 4 + 2];
            float a3 = As[kk][ty * 4 + 3];
            float b0 = Bs[kk][tx * 4 + 0];
            float b1 = Bs[kk][tx * 4 + 1];
            float b2 = Bs[kk][tx * 4 + 2];
            float b3 = Bs[kk][tx * 4 + 3];
            acc[0][0] += a0 * b0; acc[0][1] += a0 * b1; acc[0][2] += a0 * b2; acc[0][3] += a0 * b3;
            acc[1][0] += a1 * b0; acc[1][1] += a1 * b1; acc[1][2] += a1 * b2; acc[1][3] += a1 * b3;
            acc[2][0] += a2 * b0; acc[2][1] += a2 * b1; acc[2][2] += a2 * b2; acc[2][3] += a2 * b3;
            acc[3][0] += a3 * b0; acc[3][1] += a3 * b1; acc[3][2] += a3 * b2; acc[3][3] += a3 * b3;
        }
        __syncthreads();
    }

    #pragma unroll
    for (int i = 0; i < 4; i++) {
        int r = rowBase + ty * 4 + i;
        #pragma unroll
        for (int j = 0; j < 4; j++) {
            int c = colBase + tx * 4 + j;
            float val = acc[i][j];
            if (mode == 1) val += D[(size_t)r * N + c];
            else if (mode == 2) val = fmaxf(val, 0.f);
            C[(size_t)r * N + c] = val;
        }
    }
}

// ---------------- fused attention: logits (qk + qw), masked softmax, AV ----------------
// one block per (b,i), 256 threads
__global__ __launch_bounds__(256) void attn_kernel(const float* __restrict__ q,
                                                   const float* __restrict__ k,
                                                   const float* __restrict__ v,
                                                   const float* __restrict__ ew,
                                                   const int* __restrict__ adj,
                                                   float* __restrict__ o) {
    const float INV_SCALE = 0.044194173824159216f; // 1/sqrt(512)
    int bi = blockIdx.x;       // b*NN + i
    int b = bi >> 6;
    int t = threadIdx.x;

    __shared__ float qrow[HH];
    __shared__ float sl[HH];   // [h*64 + j] logits then attn

    qrow[t] = q[bi * HH + t];
    qrow[t + 256] = q[bi * HH + t + 256];
    __syncthreads();

    const float* ewbase = ew + (size_t)bi * NN * HH;
    const int* adjrow = adj + bi * NN;

    #pragma unroll
    for (int rep = 0; rep < 2; rep++) {
        int p = t + rep * 256;
        int h = p >> 6, j = p & 63;
        float logit;
        if (adjrow[j] > 0) {
            const float* kr = k + (size_t)(b * NN + j) * HH + h * 64;
            const float* er = ewbase + (size_t)j * HH + h * 64;
            float s = 0.f;
            #pragma unroll 8
            for (int d = 0; d < 64; d++) s += qrow[h * 64 + d] * (kr[d] + er[d]);
            logit = s * INV_SCALE;
        } else {
            logit = -INFINITY;
        }
        sl[p] = logit;
    }
    __syncthreads();

    // softmax per head: warp w handles head w (8 warps, 8 heads)
    int w = t >> 5, lane = t & 31;
    float x0 = sl[w * 64 + lane], x1 = sl[w * 64 + lane + 32];
    float m = fmaxf(x0, x1);
    #pragma unroll
    for (int off = 16; off > 0; off >>= 1) m = fmaxf(m, __shfl_xor_sync(0xffffffffu, m, off));
    float e0 = expf(x0 - m), e1 = expf(x1 - m);
    float se = warpReduceSum(e0 + e1);
    float inv = 1.f / se;
    sl[w * 64 + lane] = e0 * inv;
    sl[w * 64 + lane + 32] = e1 * inv;
    __syncthreads();

    #pragma unroll
    for (int rep = 0; rep < 2; rep++) {
        int p = t + rep * 256;
        int h = p >> 6, d = p & 63;
        float s = 0.f;
        #pragma unroll 8
        for (int j = 0; j < 64; j++)
            s += sl[h * 64 + j] * v[(size_t)(b * NN + j) * HH + h * 64 + d];
        o[bi * HH + p] = s;
    }
}

// ---------------- edge attention update ----------------
// one block per (b,i,j), 256 threads; reads ew, x; writes bond in place
__global__ __launch_bounds__(256) void edge_kernel(const float* __restrict__ ew,
                                                   const float* __restrict__ x,
                                                   float* __restrict__ bond) {
    const float INV_SCALE = 0.044194173824159216f;
    int bij = blockIdx.x;              // b*NN*NN + i*NN + j
    int j = bij & 63;
    int bi = bij >> 6;                 // b*NN + i
    int b = bi >> 6;

    int t = threadIdx.x;
    int lane = t & 31, w = t >> 5;

    const float* e = ew + (size_t)bij * HH;
    const float* xi = x + (size_t)bi * HH;
    const float* xj = x + (size_t)(b * NN + j) * HH;

    float e0 = e[t], e1 = e[t + 256];
    float a0 = xi[t], a1 = xi[t + 256];
    float c0 = xj[t], c1 = xj[t + 256];

    float s0 = e0 * e0 + e1 * e1;
    float s1 = e0 * a0 + e1 * a1;
    float s2 = e0 * c0 + e1 * c1;
    s0 = warpReduceSum(s0);
    s1 = warpReduceSum(s1);
    s2 = warpReduceSum(s2);

    __shared__ float red[3][8];
    if (lane == 0) { red[0][w] = s0; red[1][w] = s1; red[2][w] = s2; }
    __syncthreads();
    if (t < 3) {
        float tot = 0.f;
        #pragma unroll
        for (int q2 = 0; q2 < 8; q2++) tot += red[t][q2];
        red[t][0] = tot;
    }
    __syncthreads();

    float m0 = red[0][0] * INV_SCALE;
    float m1 = red[1][0] * INV_SCALE;
    float m2 = red[2][0] * INV_SCALE;
    float mm = fmaxf(m0, fmaxf(m1, m2));
    float q0 = expf(m0 - mm), q1 = expf(m1 - mm), q2 = expf(m2 - mm);
    float inv = 1.f / (q0 + q1 + q2);
    float w0 = q0 * inv, w1 = q1 * inv, w2 = q2 * inv;

    bond[(size_t)bij * HH + t] = w0 * e0 + w1 * a0 + w2 * c0;
    bond[(size_t)bij * HH + t + 256] = w0 * e1 + w1 * a1 + w2 * c1;
}

// ---------------- head: tanh(x[:,0]@Wout) @ Wpred + bpred -> softmax ----------------
__global__ __launch_bounds__(512) void head_kernel(const float* __restrict__ x,
                                                   const float* __restrict__ Wout,
                                                   const float* __restrict__ Wpred,
                                                   const float* __restrict__ bpred,
                                                   float* __restrict__ out) {
    int b = blockIdx.x;
    int t = threadIdx.x; // 512
    __shared__ float xb[HH];
    __shared__ float cvec[HH];
    __shared__ float r0[16], r1[16];

    xb[t] = x[(size_t)(b * NN) * HH + t];
    __syncthreads();

    float s = 0.f;
    #pragma unroll 8
    for (int h2 = 0; h2 < HH; h2++) s += xb[h2] * Wout[(size_t)h2 * HH + t];
    cvec[t] = tanhf(s);
    __syncthreads();

    float p0 = cvec[t] * Wpred[t * 2 + 0];
    float p1 = cvec[t] * Wpred[t * 2 + 1];
    p0 = warpReduceSum(p0);
    p1 = warpReduceSum(p1);
    int lane = t & 31, w = t >> 5;
    if (lane == 0) { r0[w] = p0; r1[w] = p1; }
    __syncthreads();
    if (t == 0) {
        float l0 = bpred[0], l1 = bpred[1];
        #pragma unroll
        for (int q2 = 0; q2 < 16; q2++) { l0 += r0[q2]; l1 += r1[q2]; }
        float m = fmaxf(l0, l1);
        float e0 = expf(l0 - m), e1 = expf(l1 - m);
        float inv = 1.f / (e0 + e1);
        out[b * 2 + 0] = e0 * inv;
        out[b * 2 + 1] = e1 * inv;
    }
}

// ---------------- orchestration ----------------
extern "C" void kernel_launch(void* const* d_in, const int* in_sizes, int n_in,
                              void* d_out, int out_size) {
    const int* input_batch = (const int*)d_in[0];
    const int* adj = (const int*)d_in[1];
    const float* atom_emb = (const float*)d_in[2];
    const float* bond_emb = (const float*)d_in[3];
    const float* Wq = (const float*)d_in[4];
    const float* Wk = (const float*)d_in[5];
    const float* Wv = (const float*)d_in[6];
    const float* Wew = (const float*)d_in[7];
    const float* Wstack = (const float*)d_in[8];
    const float* Wf1 = (const float*)d_in[9];
    const float* Wf2 = (const float*)d_in[10];
    const float* Wout = (const float*)d_in[11];
    const float* Wpred = (const float*)d_in[12];
    const float* bpred = (const float*)d_in[13];
    float* out = (float*)d_out;

    float *x, *xn, *q, *k, *v, *o, *resid, *h1, *ff, *bond, *ew;
    cudaGetSymbolAddress((void**)&x, g_x);
    cudaGetSymbolAddress((void**)&xn, g_xn);
    cudaGetSymbolAddress((void**)&q, g_q);
    cudaGetSymbolAddress((void**)&k, g_k);
    cudaGetSymbolAddress((void**)&v, g_v);
    cudaGetSymbolAddress((void**)&o, g_o);
    cudaGetSymbolAddress((void**)&resid, g_resid);
    cudaGetSymbolAddress((void**)&h1, g_h1);
    cudaGetSymbolAddress((void**)&ff, g_ff);
    cudaGetSymbolAddress((void**)&bond, g_bond);
    cudaGetSymbolAddress((void**)&ew, g_ew);

    embed_x_kernel<<<(BB * NN * HH) / 256, 256>>>(input_batch, atom_emb, x);
    embed_bond_kernel<<<(BB * NN * NN * HH) / 256, 256>>>(adj, bond_emb, bond);

    const int M1 = BB * NN;           // 512
    const int M2 = BB * NN * NN;      // 32768
    dim3 g88(HH / GBN, M1 / GBM);     // (8, 8)
    dim3 gew(HH / GBN, M2 / GBM);     // (8, 512)
    dim3 gf1(FFD / GBN, M1 / GBM);    // (32, 8)

    for (int l = 0; l < NLAYERS; l++) {
        const float* Wq_l = Wq + (size_t)l * HH * HH;
        const float* Wk_l = Wk + (size_t)l * HH * HH;
        const float* Wv_l = Wv + (size_t)l * HH * HH;
        const float* Wew_l = Wew + (size_t)l * HH * HH;
        const float* Wst_l = Wstack + (size_t)l * HH * HH;
        const float* Wf1_l = Wf1 + (size_t)l * HH * FFD;
        const float* Wf2_l = Wf2 + (size_t)l * FFD * HH;

        ln_kernel<<<M1, 256>>>(x, xn);
        gemm_kernel<<<g88, 256>>>(xn, Wq_l, nullptr, q, M1, HH, HH, 0);
        gemm_kernel<<<g88, 256>>>(xn, Wk_l, nullptr, k, M1, HH, HH, 0);
        gemm_kernel<<<g88, 256>>>(xn, Wv_l, nullptr, v, M1, HH, HH, 0);
        gemm_kernel<<<gew, 256>>>(bond, Wew_l, nullptr, ew, M2, HH, HH, 0);
        attn_kernel<<<M1, 256>>>(q, k, v, ew, adj, o);
        gemm_kernel<<<g88, 256>>>(o, Wst_l, xn, resid, M1, HH, HH, 1);      // + xn
        ln_kernel<<<M1, 256>>>(resid, h1);
        gemm_kernel<<<gf1, 256>>>(h1, Wf1_l, nullptr, ff, M1, FFD, HH, 2);  // relu
        gemm_kernel<<<g88, 256>>>(ff, Wf2_l, resid, x, M1, HH, FFD, 1);     // + resid
        edge_kernel<<<M2, 256>>>(ew, x, bond);
    }

    head_kernel<<<BB, 512>>>(x, Wout, Wpred, bpred, out);
}

// round 3
// speedup vs baseline: 3.3257x; 3.3257x over previous
#include <cuda_runtime.h>
#include <math.h>

#define BB 8
#define NN 64
#define HH 512
#define NHEADS 8
#define SPD 64
#define NLAYERS 4
#define FFD 2048
#define NE 32768            // B*N*N edges
#define ROWS 512            // B*N
#define INV_SCALE 0.04419417382415922f  // 1/sqrt(512)

static __device__ __forceinline__ float warpReduceSum(float v) {
    #pragma unroll
    for (int o = 16; o > 0; o >>= 1) v += __shfl_xor_sync(0xffffffffu, v, o);
    return v;
}

// ---------------- scratch (device globals; zero-init, no allocation) ----------------
__device__ float g_x[ROWS * HH];
__device__ float g_xn[ROWS * HH];
__device__ float g_q[ROWS * HH];
__device__ float g_k[ROWS * HH];
__device__ float g_v[ROWS * HH];
__device__ float g_o[ROWS * HH];
__device__ float g_resid[ROWS * HH];
__device__ float g_h1[ROWS * HH];
__device__ float g_ff[ROWS * FFD];
__device__ float g_Va[3 * ROWS * HH];   // transformed node bases (ping)
__device__ float g_Vb[3 * ROWS * HH];   // transformed node bases (pong)
__device__ float g_PsiA[32 * HH];       // padded edge-type basis (ping) rows 8..31 stay 0
__device__ float g_PsiB[32 * HH];
__device__ float g_p0[NE];
__device__ float g_pi[3 * NE];
__device__ float g_pj[3 * NE];
__device__ float g_QD[4 * BB * NHEADS * NN * NN];  // [src][b][h][i][j]
__device__ float g_QPsi[ROWS * NHEADS * 8];        // [bi][h][e]
__device__ float g_PV[3 * ROWS * 8];               // [t][row][e]
__device__ float g_PX[ROWS * 8];                   // [row][e]
__device__ float g_PsiGram[32 * 8];                // [e'][e] (rows 0..7 used)
__device__ float g_G[9 * BB * NN * NN];            // [s*3+t][b][n][m]
__device__ float g_VX[3 * BB * NN * NN];           // [t][b][n][m]

// ---------------- simple init / embed ----------------
__global__ void embed_x_kernel(const int* __restrict__ ib, const float* __restrict__ emb,
                               float* __restrict__ x) {
    int idx = blockIdx.x * blockDim.x + threadIdx.x;
    int row = idx >> 9;
    int h = idx & 511;
    x[idx] = emb[ib[row] * HH + h];
}

__global__ void psi_copy_kernel(const float* __restrict__ bemb, float* __restrict__ psi) {
    int idx = blockIdx.x * blockDim.x + threadIdx.x; // 4096
    psi[idx] = bemb[idx];
}

__global__ void initp0_kernel(float* __restrict__ p0) {
    int idx = blockIdx.x * blockDim.x + threadIdx.x;
    p0[idx] = 1.0f;
}

// ---------------- LayerNorm ----------------
__global__ void ln_kernel(const float* __restrict__ in, float* __restrict__ out) {
    __shared__ float sh[8];
    int row = blockIdx.x;
    int t = threadIdx.x; // 256
    const float* r = in + row * HH;
    float v0 = r[t], v1 = r[t + 256];
    int lane = t & 31, w = t >> 5;
    float s = warpReduceSum(v0 + v1);
    if (lane == 0) sh[w] = s;
    __syncthreads();
    if (w == 0) {
        float x = (lane < 8) ? sh[lane] : 0.f;
        x = warpReduceSum(x);
        if (lane == 0) sh[0] = x;
    }
    __syncthreads();
    float mean = sh[0] * (1.f / HH);
    __syncthreads();
    float d0 = v0 - mean, d1 = v1 - mean;
    float vs = warpReduceSum(d0 * d0 + d1 * d1);
    if (lane == 0) sh[w] = vs;
    __syncthreads();
    if (w == 0) {
        float x = (lane < 8) ? sh[lane] : 0.f;
        x = warpReduceSum(x);
        if (lane == 0) sh[0] = x;
    }
    __syncthreads();
    float rinv = rsqrtf(sh[0] * (1.f / HH) + 1e-5f);
    out[row * HH + t] = d0 * rinv;
    out[row * HH + t + 256] = d1 * rinv;
}

// ---------------- batched-job 32x64 SGEMM ----------------
// mode 0: C = AB ; 1: C = AB + D ; 2: C = relu(AB)
struct GJob {
    const float* A; const float* B; const float* D; float* C;
    int M, N, K, mode, blkStart;
};
struct GParams { GJob jobs[8]; int nJobs; };

__global__ __launch_bounds__(256) void gemm32_kernel(GParams P) {
    int bx = blockIdx.x;
    int jb = 0;
    #pragma unroll
    for (int t = 1; t < 8; t++)
        if (t < P.nJobs && bx >= P.jobs[t].blkStart) jb = t;
    GJob job = P.jobs[jb];
    int tile = bx - job.blkStart;
    int tilesN = job.N >> 6;
    int tm = tile / tilesN, tn = tile - tm * tilesN;
    int N = job.N, K = job.K;
    int rowBase = tm * 32, colBase = tn * 64;

    __shared__ float As[16][32];
    __shared__ float Bs[16][64];
    int tid = threadIdx.x;
    int tx = tid & 15, ty = tid >> 4;

    float acc[2][4];
    #pragma unroll
    for (int u = 0; u < 2; u++)
        #pragma unroll
        for (int w = 0; w < 4; w++) acc[u][w] = 0.f;

    for (int k0 = 0; k0 < K; k0 += 16) {
        #pragma unroll
        for (int r = 0; r < 2; r++) {
            int idx = tid + r * 256;
            int m = idx >> 4, kk = idx & 15;
            As[kk][m] = job.A[(size_t)(rowBase + m) * K + k0 + kk];
        }
        #pragma unroll
        for (int r = 0; r < 4; r++) {
            int idx = tid + r * 256;
            int kk = idx >> 6, n = idx & 63;
            Bs[kk][n] = job.B[(size_t)(k0 + kk) * N + colBase + n];
        }
        __syncthreads();
        #pragma unroll
        for (int kk = 0; kk < 16; kk++) {
            float a0 = As[kk][ty * 2], a1 = As[kk][ty * 2 + 1];
            float4 b4 = *(const float4*)&Bs[kk][tx * 4];
            acc[0][0] += a0 * b4.x; acc[0][1] += a0 * b4.y;
            acc[0][2] += a0 * b4.z; acc[0][3] += a0 * b4.w;
            acc[1][0] += a1 * b4.x; acc[1][1] += a1 * b4.y;
            acc[1][2] += a1 * b4.z; acc[1][3] += a1 * b4.w;
        }
        __syncthreads();
    }
    #pragma unroll
    for (int u = 0; u < 2; u++) {
        int r = rowBase + ty * 2 + u;
        #pragma unroll
        for (int w = 0; w < 4; w++) {
            int c = colBase + tx * 4 + w;
            float val = acc[u][w];
            if (job.mode == 1) val += job.D[(size_t)r * N + c];
            else if (job.mode == 2) val = fmaxf(val, 0.f);
            job.C[(size_t)r * N + c] = val;
        }
    }
}

// ---------------- per-head [64,64] einsum: QD[src][b,h,i,j] = q_i|h . S_j|h ----------------
__global__ __launch_bounds__(256) void qd_kernel(const float* __restrict__ q,
                                                 const float* __restrict__ k,
                                                 const float* v0, const float* v1, const float* v2,
                                                 float* __restrict__ QD) {
    int bh = blockIdx.x;          // b*8+h
    int src = blockIdx.y;
    int b = bh >> 3, h = bh & 7;
    const float* S = (src == 0) ? k : (src == 1 ? v0 : (src == 2 ? v1 : v2));

    __shared__ float Qs[64][65];
    __shared__ float Ss[64][65];
    int tid = threadIdx.x;
    #pragma unroll
    for (int r = 0; r < 16; r++) {
        int idx = tid + r * 256;
        int i = idx >> 6, d = idx & 63;
        size_t g = (size_t)(b * 64 + i) * HH + h * 64 + d;
        Qs[i][d] = q[g];
        Ss[i][d] = S[g];
    }
    __syncthreads();
    int tx = tid & 15, ty = tid >> 4;
    float acc[4][4];
    #pragma unroll
    for (int u = 0; u < 4; u++)
        #pragma unroll
        for (int w = 0; w < 4; w++) acc[u][w] = 0.f;
    #pragma unroll 4
    for (int d = 0; d < 64; d++) {
        float a0 = Qs[ty * 4 + 0][d], a1 = Qs[ty * 4 + 1][d];
        float a2 = Qs[ty * 4 + 2][d], a3 = Qs[ty * 4 + 3][d];
        float b0 = Ss[tx * 4 + 0][d], b1 = Ss[tx * 4 + 1][d];
        float b2 = Ss[tx * 4 + 2][d], b3 = Ss[tx * 4 + 3][d];
        acc[0][0] += a0 * b0; acc[0][1] += a0 * b1; acc[0][2] += a0 * b2; acc[0][3] += a0 * b3;
        acc[1][0] += a1 * b0; acc[1][1] += a1 * b1; acc[1][2] += a1 * b2; acc[1][3] += a1 * b3;
        acc[2][0] += a2 * b0; acc[2][1] += a2 * b1; acc[2][2] += a2 * b2; acc[2][3] += a2 * b3;
        acc[3][0] += a3 * b0; acc[3][1] += a3 * b1; acc[3][2] += a3 * b2; acc[3][3] += a3 * b3;
    }
    float* out = QD + ((size_t)src * 64 + bh) * 4096;
    #pragma unroll
    for (int u = 0; u < 4; u++)
        #pragma unroll
        for (int w = 0; w < 4; w++)
            out[(ty * 4 + u) * 64 + tx * 4 + w] = acc[u][w];
}

// ---------------- QPsi[bi][h][e] = q_bi|h . Psi'[e]|h ----------------
__global__ void qpsi_kernel(const float* __restrict__ q, const float* __restrict__ Psi,
                            float* __restrict__ QPsi) {
    int bi = blockIdx.x;
    int t = threadIdx.x; // 64
    __shared__ float qs[HH];
    #pragma unroll
    for (int r = 0; r < 8; r++) qs[t + r * 64] = q[(size_t)bi * HH + t + r * 64];
    __syncthreads();
    int h = t >> 3, e = t & 7;
    float s = 0.f;
    #pragma unroll 8
    for (int d = 0; d < 64; d++) s += qs[h * 64 + d] * Psi[e * HH + h * 64 + d];
    QPsi[bi * 64 + t] = s;
}

// ---------------- attention: assemble logits from scalars, softmax, AV ----------------
__global__ __launch_bounds__(256) void attn_kernel(const float* __restrict__ QD,
                                                   const float* __restrict__ QPsi,
                                                   const float* __restrict__ v,
                                                   const int* __restrict__ adj,
                                                   const float* __restrict__ p0,
                                                   const float* __restrict__ pi,
                                                   const float* __restrict__ pj,
                                                   int T,
                                                   float* __restrict__ o) {
    int bi = blockIdx.x;
    int b = bi >> 6, i = bi & 63;
    int t = threadIdx.x;
    __shared__ float sl[HH];
    const int* adjrow = adj + bi * NN;

    #pragma unroll
    for (int rep = 0; rep < 2; rep++) {
        int p = t + rep * 256;
        int h = p >> 6, j = p & 63;
        int e = adjrow[j];
        float lg;
        if (e > 0) {
            int bij = bi * 64 + j;
            size_t base = ((size_t)(b * 8 + h) * 64 + i) * 64;
            lg = QD[base + j];
            lg += p0[bij] * QPsi[(bi * 8 + h) * 8 + e];
            for (int tt = 0; tt < T; tt++) {
                const float* qd = QD + (size_t)(tt + 1) * 262144 + base;
                lg += pi[tt * NE + bij] * qd[i] + pj[tt * NE + bij] * qd[j];
            }
            lg *= INV_SCALE;
        } else {
            lg = -INFINITY;
        }
        sl[p] = lg;
    }
    __syncthreads();

    int w = t >> 5, lane = t & 31;
    float x0 = sl[w * 64 + lane], x1 = sl[w * 64 + lane + 32];
    float m = fmaxf(x0, x1);
    #pragma unroll
    for (int off = 16; off > 0; off >>= 1) m = fmaxf(m, __shfl_xor_sync(0xffffffffu, m, off));
    float e0 = expf(x0 - m), e1 = expf(x1 - m);
    float se = warpReduceSum(e0 + e1);
    float inv = 1.f / se;
    sl[w * 64 + lane] = e0 * inv;
    sl[w * 64 + lane + 32] = e1 * inv;
    __syncthreads();

    #pragma unroll
    for (int rep = 0; rep < 2; rep++) {
        int p = t + rep * 256;
        int h = p >> 6, d = p & 63;
        float s = 0.f;
        #pragma unroll 8
        for (int j = 0; j < 64; j++)
            s += sl[h * 64 + j] * v[(size_t)(b * 64 + j) * HH + h * 64 + d];
        o[(size_t)bi * HH + p] = s;
    }
}

// ---------------- batched [64,64] Gram: C[b,n,m] = A[b,n,:] . B[b,m,:] over 512 ----------------
struct DJob { const float* A; const float* B; float* C; };
struct DParams { DJob jobs[6]; int n; };
__global__ __launch_bounds__(256) void gram_kernel(DParams P) {
    DJob job = P.jobs[blockIdx.x];
    int b = blockIdx.y;
    __shared__ float As[64][33];
    __shared__ float Bs2[64][33];
    int tid = threadIdx.x;
    int tx = tid & 15, ty = tid >> 4;
    float acc[4][4];
    #pragma unroll
    for (int u = 0; u < 4; u++)
        #pragma unroll
        for (int w = 0; w < 4; w++) acc[u][w] = 0.f;

    for (int kc = 0; kc < 16; kc++) {
        #pragma unroll
        for (int r = 0; r < 8; r++) {
            int idx = tid + r * 256;
            int n = idx >> 5, kk = idx & 31;
            As[n][kk] = job.A[(size_t)(b * 64 + n) * HH + kc * 32 + kk];
            Bs2[n][kk] = job.B[(size_t)(b * 64 + n) * HH + kc * 32 + kk];
        }
        __syncthreads();
        #pragma unroll 8
        for (int kk = 0; kk < 32; kk++) {
            float a0 = As[ty * 4 + 0][kk], a1 = As[ty * 4 + 1][kk];
            float a2 = As[ty * 4 + 2][kk], a3 = As[ty * 4 + 3][kk];
            float b0 = Bs2[tx * 4 + 0][kk], b1 = Bs2[tx * 4 + 1][kk];
            float b2 = Bs2[tx * 4 + 2][kk], b3 = Bs2[tx * 4 + 3][kk];
            acc[0][0] += a0 * b0; acc[0][1] += a0 * b1; acc[0][2] += a0 * b2; acc[0][3] += a0 * b3;
            acc[1][0] += a1 * b0; acc[1][1] += a1 * b1; acc[1][2] += a1 * b2; acc[1][3] += a1 * b3;
            acc[2][0] += a2 * b0; acc[2][1] += a2 * b1; acc[2][2] += a2 * b2; acc[2][3] += a2 * b3;
            acc[3][0] += a3 * b0; acc[3][1] += a3 * b1; acc[3][2] += a3 * b2; acc[3][3] += a3 * b3;
        }
        __syncthreads();
    }
    float* out = job.C + (size_t)b * 4096;
    #pragma unroll
    for (int u = 0; u < 4; u++)
        #pragma unroll
        for (int w = 0; w < 4; w++)
            out[(ty * 4 + u) * 64 + tx * 4 + w] = acc[u][w];
}

// ---------------- psidot: C[row][e] = A[row,:] . Psi[e,:] ----------------
struct PJob { const float* A; float* C; int rows; };
struct PParams { PJob jobs[4]; int n; };
__global__ void psidot_kernel(PParams P, const float* __restrict__ Psi) {
    PJob job = P.jobs[blockIdx.x];
    int row = blockIdx.y;
    if (row >= job.rows) return;
    int t = threadIdx.x; // 256
    int w = t >> 5, lane = t & 31;
    float s = 0.f;
    #pragma unroll
    for (int u = 0; u < 16; u++) {
        int d = lane + u * 32;
        s += job.A[(size_t)row * HH + d] * Psi[w * HH + d];
    }
    s = warpReduceSum(s);
    if (lane == 0) job.C[row * 8 + w] = s;
}

// ---------------- edge coefficient update ----------------
__global__ void edge_kernel(const int* __restrict__ adj,
                            const float* __restrict__ PsiGram,
                            const float* __restrict__ PV,
                            const float* __restrict__ PX,
                            const float* __restrict__ G,
                            const float* __restrict__ VX,
                            float* __restrict__ p0,
                            float* __restrict__ pi,
                            float* __restrict__ pj,
                            int T) {
    int bij = blockIdx.x * blockDim.x + threadIdx.x; // 32768
    int b = bij >> 12;
    int ij = bij & 4095;
    int i = ij >> 6, j = ij & 63;
    int e = adj[bij];
    int ni = b * 64 + i, nj = b * 64 + j;

    float P0 = p0[bij];
    float s = P0 * P0 * PsiGram[e * 8 + e];
    float a0 = P0 * PX[ni * 8 + e];
    float a1 = P0 * PX[nj * 8 + e];

    float ci[3], cj[3];
    for (int t = 0; t < T; t++) { ci[t] = pi[t * NE + bij]; cj[t] = pj[t * NE + bij]; }

    for (int t = 0; t < T; t++) {
        s += 2.f * P0 * (ci[t] * PV[t * (ROWS * 8) + ni * 8 + e] +
                         cj[t] * PV[t * (ROWS * 8) + nj * 8 + e]);
        const float* vx = VX + (size_t)t * NE + (size_t)b * 4096;
        a0 += ci[t] * vx[i * 64 + i] + cj[t] * vx[j * 64 + i];
        a1 += ci[t] * vx[i * 64 + j] + cj[t] * vx[j * 64 + j];
        for (int ss2 = 0; ss2 < T; ss2++) {
            const float* g = G + (size_t)(ss2 * 3 + t) * NE + (size_t)b * 4096;
            s += ci[ss2] * ci[t] * g[i * 64 + i]
               + cj[ss2] * cj[t] * g[j * 64 + j]
               + 2.f * ci[ss2] * cj[t] * g[i * 64 + j];
        }
    }

    float u0 = s * INV_SCALE, u1 = a0 * INV_SCALE, u2 = a1 * INV_SCALE;
    float mm = fmaxf(u0, fmaxf(u1, u2));
    float q0 = expf(u0 - mm), q1 = expf(u1 - mm), q2 = expf(u2 - mm);
    float inv = 1.f / (q0 + q1 + q2);
    float w0 = q0 * inv;

    p0[bij] = w0 * P0;
    for (int t = 0; t < T; t++) {
        pi[t * NE + bij] = w0 * ci[t];
        pj[t * NE + bij] = w0 * cj[t];
    }
    pi[T * NE + bij] = q1 * inv;
    pj[T * NE + bij] = q2 * inv;
}

// ---------------- head ----------------
__global__ __launch_bounds__(512) void head_kernel(const float* __restrict__ x,
                                                   const float* __restrict__ Wout,
                                                   const float* __restrict__ Wpred,
                                                   const float* __restrict__ bpred,
                                                   float* __restrict__ out) {
    int b = blockIdx.x;
    int t = threadIdx.x; // 512
    __shared__ float xb[HH];
    __shared__ float cvec[HH];
    __shared__ float r0[16], r1[16];
    xb[t] = x[(size_t)(b * NN) * HH + t];
    __syncthreads();
    float s = 0.f;
    #pragma unroll 8
    for (int h2 = 0; h2 < HH; h2++) s += xb[h2] * Wout[(size_t)h2 * HH + t];
    cvec[t] = tanhf(s);
    __syncthreads();
    float pr0 = cvec[t] * Wpred[t * 2 + 0];
    float pr1 = cvec[t] * Wpred[t * 2 + 1];
    pr0 = warpReduceSum(pr0);
    pr1 = warpReduceSum(pr1);
    int lane = t & 31, w = t >> 5;
    if (lane == 0) { r0[w] = pr0; r1[w] = pr1; }
    __syncthreads();
    if (t == 0) {
        float l0 = bpred[0], l1 = bpred[1];
        #pragma unroll
        for (int q2 = 0; q2 < 16; q2++) { l0 += r0[q2]; l1 += r1[q2]; }
        float m = fmaxf(l0, l1);
        float e0 = expf(l0 - m), e1 = expf(l1 - m);
        float inv = 1.f / (e0 + e1);
        out[b * 2 + 0] = e0 * inv;
        out[b * 2 + 1] = e1 * inv;
    }
}

// ---------------- orchestration ----------------
extern "C" void kernel_launch(void* const* d_in, const int* in_sizes, int n_in,
                              void* d_out, int out_size) {
    const int* input_batch = (const int*)d_in[0];
    const int* adj = (const int*)d_in[1];
    const float* atom_emb = (const float*)d_in[2];
    const float* bond_emb = (const float*)d_in[3];
    const float* Wq = (const float*)d_in[4];
    const float* Wk = (const float*)d_in[5];
    const float* Wv = (const float*)d_in[6];
    const float* Wew = (const float*)d_in[7];
    const float* Wstack = (const float*)d_in[8];
    const float* Wf1 = (const float*)d_in[9];
    const float* Wf2 = (const float*)d_in[10];
    const float* Wout = (const float*)d_in[11];
    const float* Wpred = (const float*)d_in[12];
    const float* bpred = (const float*)d_in[13];
    float* out = (float*)d_out;

    float *x, *xn, *q, *k, *v, *o, *resid, *h1, *ff, *Va, *Vb, *PsiA, *PsiB;
    float *p0, *pi, *pj, *QD, *QPsi, *PV, *PX, *PsiGram, *G, *VX;
    cudaGetSymbolAddress((void**)&x, g_x);
    cudaGetSymbolAddress((void**)&xn, g_xn);
    cudaGetSymbolAddress((void**)&q, g_q);
    cudaGetSymbolAddress((void**)&k, g_k);
    cudaGetSymbolAddress((void**)&v, g_v);
    cudaGetSymbolAddress((void**)&o, g_o);
    cudaGetSymbolAddress((void**)&resid, g_resid);
    cudaGetSymbolAddress((void**)&h1, g_h1);
    cudaGetSymbolAddress((void**)&ff, g_ff);
    cudaGetSymbolAddress((void**)&Va, g_Va);
    cudaGetSymbolAddress((void**)&Vb, g_Vb);
    cudaGetSymbolAddress((void**)&PsiA, g_PsiA);
    cudaGetSymbolAddress((void**)&PsiB, g_PsiB);
    cudaGetSymbolAddress((void**)&p0, g_p0);
    cudaGetSymbolAddress((void**)&pi, g_pi);
    cudaGetSymbolAddress((void**)&pj, g_pj);
    cudaGetSymbolAddress((void**)&QD, g_QD);
    cudaGetSymbolAddress((void**)&QPsi, g_QPsi);
    cudaGetSymbolAddress((void**)&PV, g_PV);
    cudaGetSymbolAddress((void**)&PX, g_PX);
    cudaGetSymbolAddress((void**)&PsiGram, g_PsiGram);
    cudaGetSymbolAddress((void**)&G, g_G);
    cudaGetSymbolAddress((void**)&VX, g_VX);

    embed_x_kernel<<<ROWS * HH / 256, 256>>>(input_batch, atom_emb, x);
    psi_copy_kernel<<<16, 256>>>(bond_emb, PsiA);
    initp0_kernel<<<NE / 256, 256>>>(p0);

    float* VbufA[3] = {Va, Va + ROWS * HH, Va + 2 * ROWS * HH};
    float* VbufB[3] = {Vb, Vb + ROWS * HH, Vb + 2 * ROWS * HH};
    float* prevDst[3] = {nullptr, nullptr, nullptr};

    for (int l = 0; l < NLAYERS; l++) {
        const float* Wq_l = Wq + (size_t)l * HH * HH;
        const float* Wk_l = Wk + (size_t)l * HH * HH;
        const float* Wv_l = Wv + (size_t)l * HH * HH;
        const float* Wew_l = Wew + (size_t)l * HH * HH;
        const float* Wst_l = Wstack + (size_t)l * HH * HH;
        const float* Wf1_l = Wf1 + (size_t)l * HH * FFD;
        const float* Wf2_l = Wf2 + (size_t)l * FFD * HH;

        int T = l;
        float** dst = (l & 1) ? VbufA : VbufB;
        const float* src[3];
        for (int t = 0; t < T - 1; t++) src[t] = prevDst[t];
        if (T > 0) src[T - 1] = x;
        float* psiSrc = (l & 1) ? PsiB : PsiA;
        float* psiDst = (l & 1) ? PsiA : PsiB;

        // 1) LN
        ln_kernel<<<ROWS, 256>>>(x, xn);

        // 2) fused GEMMs: q,k,v + V'_t + Psi'
        {
            GParams P;
            int nb = 0, blk = 0;
            auto add = [&](const float* A, const float* B2, const float* D2, float* C2,
                           int M, int N2, int K2, int mode) {
                P.jobs[nb] = {A, B2, D2, C2, M, N2, K2, mode, blk};
                blk += (M / 32) * (N2 / 64);
                nb++;
            };
            add(xn, Wq_l, nullptr, q, ROWS, HH, HH, 0);
            add(xn, Wk_l, nullptr, k, ROWS, HH, HH, 0);
            add(xn, Wv_l, nullptr, v, ROWS, HH, HH, 0);
            for (int t = 0; t < T; t++) add(src[t], Wew_l, nullptr, dst[t], ROWS, HH, HH, 0);
            add(psiSrc, Wew_l, nullptr, psiDst, 32, HH, HH, 0);
            P.nJobs = nb;
            gemm32_kernel<<<blk, 256>>>(P);
        }

        // 3) per-head einsums QD[0..T]
        {
            dim3 g(BB * NHEADS, 1 + T);
            qd_kernel<<<g, 256>>>(q, k, T > 0 ? dst[0] : nullptr,
                                  T > 1 ? dst[1] : nullptr, T > 2 ? dst[2] : nullptr, QD);
        }

        // 4) QPsi
        qpsi_kernel<<<ROWS, 64>>>(q, psiDst, QPsi);

        // 5) attention
        attn_kernel<<<ROWS, 256>>>(QD, QPsi, v, adj, p0, pi, pj, T, o);

        // 6) stack (+xn)
        {
            GParams P;
            P.jobs[0] = {o, Wst_l, xn, resid, ROWS, HH, HH, 1, 0};
            P.nJobs = 1;
            gemm32_kernel<<<(ROWS / 32) * (HH / 64), 256>>>(P);
        }

        // 7) LN
        ln_kernel<<<ROWS, 256>>>(resid, h1);

        // 8) FF1 (relu)
        {
            GParams P;
            P.jobs[0] = {h1, Wf1_l, nullptr, ff, ROWS, FFD, HH, 2, 0};
            P.nJobs = 1;
            gemm32_kernel<<<(ROWS / 32) * (FFD / 64), 256>>>(P);
        }
        // 9) FF2 (+resid) -> x
        {
            GParams P;
            P.jobs[0] = {ff, Wf2_l, resid, x, ROWS, HH, FFD, 1, 0};
            P.nJobs = 1;
            gemm32_kernel<<<(ROWS / 32) * (HH / 64), 256>>>(P);
        }

        if (l < NLAYERS - 1) {
            // 10) Gram matrices G[s,t] and VX[t]
            int nj = 0;
            DParams DP;
            for (int s = 0; s < T; s++)
                for (int t = 0; t < T; t++)
                    DP.jobs[nj++] = {dst[s], dst[t], G + (size_t)(s * 3 + t) * NE};
            for (int t = 0; t < T; t++)
                DP.jobs[nj++] = {dst[t], x, VX + (size_t)t * NE};
            DP.n = nj;
            if (nj > 0) {
                dim3 g(nj, BB);
                gram_kernel<<<g, 256>>>(DP);
            }

            // 11) psidot: PV_t, PX, PsiGram
            {
                PParams PP2;
                int np = 0;
                for (int t = 0; t < T; t++) PP2.jobs[np++] = {dst[t], PV + t * (ROWS * 8), ROWS};
                PP2.jobs[np++] = {x, PX, ROWS};
                PP2.jobs[np++] = {psiDst, PsiGram, 32};
                PP2.n = np;
                dim3 g(np, ROWS);
                psidot_kernel<<<g, 256>>>(PP2, psiDst);
            }

            // 12) edge coefficient update
            edge_kernel<<<NE / 256, 256>>>(adj, PsiGram, PV, PX, G, VX, p0, pi, pj, T);
        }

        prevDst[0] = dst[0]; prevDst[1] = dst[1]; prevDst[2] = dst[2];
    }

    head_kernel<<<BB, 512>>>(x, Wout, Wpred, bpred, out);
}

// round 4
// speedup vs baseline: 6.1884x; 1.8608x over previous
#include <cuda_runtime.h>
#include <math.h>
#include <stdint.h>

#define BB 8
#define NN 64
#define HH 512
#define NHEADS 8
#define SPD 64
#define NLAYERS 4
#define FFD 2048
#define NE 32768            // B*N*N edges
#define ROWS 512            // B*N
#define INV_SCALE 0.04419417382415922f  // 1/sqrt(512)

static __device__ __forceinline__ float warpReduceSum(float v) {
    #pragma unroll
    for (int o = 16; o > 0; o >>= 1) v += __shfl_xor_sync(0xffffffffu, v, o);
    return v;
}

static __device__ __forceinline__ uint32_t f2tf32(float f) {
    uint32_t u;
    asm("cvt.rna.tf32.f32 %0, %1;" : "=r"(u) : "f"(f));
    return u;
}

static __device__ __forceinline__ void mma_tf32(float* c, const uint32_t* a, const uint32_t* b) {
    asm volatile("mma.sync.aligned.m16n8k8.row.col.f32.tf32.tf32.f32 "
                 "{%0,%1,%2,%3}, {%4,%5,%6,%7}, {%8,%9}, {%0,%1,%2,%3};"
                 : "+f"(c[0]), "+f"(c[1]), "+f"(c[2]), "+f"(c[3])
                 : "r"(a[0]), "r"(a[1]), "r"(a[2]), "r"(a[3]), "r"(b[0]), "r"(b[1]));
}

// ---------------- scratch (device globals; zero-init, no allocation) ----------------
__device__ float g_x[ROWS * HH];
__device__ float g_xn[ROWS * HH];
__device__ float g_q[ROWS * HH];
__device__ float g_k[ROWS * HH];
__device__ float g_v[ROWS * HH];
__device__ float g_o[ROWS * HH];
__device__ float g_resid[ROWS * HH];
__device__ float g_h1[ROWS * HH];
__device__ float g_ff[ROWS * FFD];
__device__ float g_Va[3 * ROWS * HH];
__device__ float g_Vb[3 * ROWS * HH];
__device__ float g_PsiA[64 * HH];       // rows 8..63 stay 0
__device__ float g_PsiB[64 * HH];
__device__ float g_p0[NE];
__device__ float g_pi[3 * NE];
__device__ float g_pj[3 * NE];
__device__ float g_QD[4 * BB * NHEADS * NN * NN];  // [src][b][h][i][j]
__device__ float g_QPsi[ROWS * NHEADS * 8];        // [bi][h][e]
__device__ float g_PV[3 * ROWS * 8];               // [t][row][e]
__device__ float g_PX[ROWS * 8];                   // [row][e]
__device__ float g_PsiGram[64 * 8];                // rows 0..7 used
__device__ float g_G[9 * BB * NN * NN];            // [s*3+t][b][n][m]
__device__ float g_VX[3 * BB * NN * NN];           // [t][b][n][m]

// ---------------- simple init / embed ----------------
__global__ void embed_x_kernel(const int* __restrict__ ib, const float* __restrict__ emb,
                               float* __restrict__ x) {
    int idx = blockIdx.x * blockDim.x + threadIdx.x;
    int row = idx >> 9;
    int h = idx & 511;
    x[idx] = emb[ib[row] * HH + h];
}

__global__ void psi_copy_kernel(const float* __restrict__ bemb, float* __restrict__ psi) {
    int idx = blockIdx.x * blockDim.x + threadIdx.x; // 4096
    psi[idx] = bemb[idx];
}

__global__ void initp0_kernel(float* __restrict__ p0) {
    int idx = blockIdx.x * blockDim.x + threadIdx.x;
    p0[idx] = 1.0f;
}

// ---------------- LayerNorm ----------------
__global__ void ln_kernel(const float* __restrict__ in, float* __restrict__ out) {
    __shared__ float sh[8];
    int row = blockIdx.x;
    int t = threadIdx.x; // 256
    const float* r = in + row * HH;
    float v0 = r[t], v1 = r[t + 256];
    int lane = t & 31, w = t >> 5;
    float s = warpReduceSum(v0 + v1);
    if (lane == 0) sh[w] = s;
    __syncthreads();
    if (w == 0) {
        float x = (lane < 8) ? sh[lane] : 0.f;
        x = warpReduceSum(x);
        if (lane == 0) sh[0] = x;
    }
    __syncthreads();
    float mean = sh[0] * (1.f / HH);
    __syncthreads();
    float d0 = v0 - mean, d1 = v1 - mean;
    float vs = warpReduceSum(d0 * d0 + d1 * d1);
    if (lane == 0) sh[w] = vs;
    __syncthreads();
    if (w == 0) {
        float x = (lane < 8) ? sh[lane] : 0.f;
        x = warpReduceSum(x);
        if (lane == 0) sh[0] = x;
    }
    __syncthreads();
    float rinv = rsqrtf(sh[0] * (1.f / HH) + 1e-5f);
    out[row * HH + t] = d0 * rinv;
    out[row * HH + t + 256] = d1 * rinv;
}

// ---------------- batched-job TF32 tensor-core GEMM (64x64x32 tiles) ----------------
// mode 0: C = AB ; 1: C = AB + D ; 2: C = relu(AB)
struct GJob {
    const float* A; const float* B; const float* D; float* C;
    int M, N, K, mode, blkStart;
};
struct GParams { GJob jobs[8]; int nJobs; };

__global__ __launch_bounds__(256) void gemm_tc_kernel(GParams P) {
    int bx = blockIdx.x;
    int jb = 0;
    #pragma unroll
    for (int t = 1; t < 8; t++)
        if (t < P.nJobs && bx >= P.jobs[t].blkStart) jb = t;
    GJob job = P.jobs[jb];
    int tile = bx - job.blkStart;
    int tilesN = job.N >> 6;
    int tm = tile / tilesN, tn = tile - tm * tilesN;
    int N = job.N, K = job.K;
    int rowBase = tm * 64, colBase = tn * 64;

    __shared__ uint32_t As[64][36];   // stride 36: 4g+t4 hits 32 distinct banks
    __shared__ uint32_t Bs[32][72];   // stride 72 (mod 32 = 8): 8t4+g distinct

    int tid = threadIdx.x;
    int lane = tid & 31, wid = tid >> 5;
    int wm = wid >> 2;        // 0..1
    int wn = wid & 3;         // 0..3
    int g = lane >> 2, t4 = lane & 3;

    float acc[2][2][4];
    #pragma unroll
    for (int mf = 0; mf < 2; mf++)
        #pragma unroll
        for (int nf = 0; nf < 2; nf++)
            #pragma unroll
            for (int r = 0; r < 4; r++) acc[mf][nf][r] = 0.f;

    int arow = tid >> 3, ac4 = tid & 7;     // A: 64 rows x 8 float4-cols
    int brow = tid >> 4, bc4 = tid & 15;    // B: 32 rows x 16 float4-cols

    for (int k0 = 0; k0 < K; k0 += 32) {
        #pragma unroll
        for (int rep = 0; rep < 2; rep++) {
            int r = arow + rep * 32;
            float4 f = *(const float4*)&job.A[(size_t)(rowBase + r) * K + k0 + ac4 * 4];
            As[r][ac4 * 4 + 0] = f2tf32(f.x);
            As[r][ac4 * 4 + 1] = f2tf32(f.y);
            As[r][ac4 * 4 + 2] = f2tf32(f.z);
            As[r][ac4 * 4 + 3] = f2tf32(f.w);
        }
        #pragma unroll
        for (int rep = 0; rep < 2; rep++) {
            int r = brow + rep * 16;
            float4 f = *(const float4*)&job.B[(size_t)(k0 + r) * N + colBase + bc4 * 4];
            Bs[r][bc4 * 4 + 0] = f2tf32(f.x);
            Bs[r][bc4 * 4 + 1] = f2tf32(f.y);
            Bs[r][bc4 * 4 + 2] = f2tf32(f.z);
            Bs[r][bc4 * 4 + 3] = f2tf32(f.w);
        }
        __syncthreads();

        #pragma unroll
        for (int ks = 0; ks < 4; ks++) {
            uint32_t a[2][4], b[2][2];
            #pragma unroll
            for (int mf = 0; mf < 2; mf++) {
                int r0 = wm * 32 + mf * 16;
                a[mf][0] = As[r0 + g][ks * 8 + t4];
                a[mf][1] = As[r0 + 8 + g][ks * 8 + t4];
                a[mf][2] = As[r0 + g][ks * 8 + t4 + 4];
                a[mf][3] = As[r0 + 8 + g][ks * 8 + t4 + 4];
            }
            #pragma unroll
            for (int nf = 0; nf < 2; nf++) {
                int c0 = wn * 16 + nf * 8;
                b[nf][0] = Bs[ks * 8 + t4][c0 + g];
                b[nf][1] = Bs[ks * 8 + t4 + 4][c0 + g];
            }
            #pragma unroll
            for (int mf = 0; mf < 2; mf++)
                #pragma unroll
                for (int nf = 0; nf < 2; nf++)
                    mma_tf32(acc[mf][nf], a[mf], b[nf]);
        }
        __syncthreads();
    }

    // write out: c0:(g, t4*2) c1:(g, t4*2+1) c2:(g+8, ..) c3
    #pragma unroll
    for (int mf = 0; mf < 2; mf++) {
        #pragma unroll
        for (int nf = 0; nf < 2; nf++) {
            int colb = colBase + wn * 16 + nf * 8 + t4 * 2;
            #pragma unroll
            for (int half = 0; half < 2; half++) {
                int row = rowBase + wm * 32 + mf * 16 + g + half * 8;
                float vx = acc[mf][nf][half * 2 + 0];
                float vy = acc[mf][nf][half * 2 + 1];
                size_t off = (size_t)row * N + colb;
                if (job.mode == 1) {
                    vx += job.D[off];
                    vy += job.D[off + 1];
                } else if (job.mode == 2) {
                    vx = fmaxf(vx, 0.f);
                    vy = fmaxf(vy, 0.f);
                }
                *(float2*)&job.C[off] = make_float2(vx, vy);
            }
        }
    }
}

// ---------------- per-head [64,64] einsum: QD[src][b,h,i,j] = q_i|h . S_j|h ----------------
__global__ __launch_bounds__(256) void qd_kernel(const float* __restrict__ q,
                                                 const float* __restrict__ k,
                                                 const float* v0, const float* v1, const float* v2,
                                                 float* __restrict__ QD) {
    int bh = blockIdx.x;          // b*8+h
    int src = blockIdx.y;
    int b = bh >> 3, h = bh & 7;
    const float* S = (src == 0) ? k : (src == 1 ? v0 : (src == 2 ? v1 : v2));

    __shared__ float Qs[64][65];
    __shared__ float Ss[64][65];
    int tid = threadIdx.x;
    #pragma unroll
    for (int r = 0; r < 16; r++) {
        int idx = tid + r * 256;
        int i = idx >> 6, d = idx & 63;
        size_t gg = (size_t)(b * 64 + i) * HH + h * 64 + d;
        Qs[i][d] = q[gg];
        Ss[i][d] = S[gg];
    }
    __syncthreads();
    int tx = tid & 15, ty = tid >> 4;
    float acc[4][4];
    #pragma unroll
    for (int u = 0; u < 4; u++)
        #pragma unroll
        for (int w = 0; w < 4; w++) acc[u][w] = 0.f;
    #pragma unroll 4
    for (int d = 0; d < 64; d++) {
        float a0 = Qs[ty * 4 + 0][d], a1 = Qs[ty * 4 + 1][d];
        float a2 = Qs[ty * 4 + 2][d], a3 = Qs[ty * 4 + 3][d];
        float b0 = Ss[tx * 4 + 0][d], b1 = Ss[tx * 4 + 1][d];
        float b2 = Ss[tx * 4 + 2][d], b3 = Ss[tx * 4 + 3][d];
        acc[0][0] += a0 * b0; acc[0][1] += a0 * b1; acc[0][2] += a0 * b2; acc[0][3] += a0 * b3;
        acc[1][0] += a1 * b0; acc[1][1] += a1 * b1; acc[1][2] += a1 * b2; acc[1][3] += a1 * b3;
        acc[2][0] += a2 * b0; acc[2][1] += a2 * b1; acc[2][2] += a2 * b2; acc[2][3] += a2 * b3;
        acc[3][0] += a3 * b0; acc[3][1] += a3 * b1; acc[3][2] += a3 * b2; acc[3][3] += a3 * b3;
    }
    float* out = QD + ((size_t)src * 64 + bh) * 4096;
    #pragma unroll
    for (int u = 0; u < 4; u++)
        #pragma unroll
        for (int w = 0; w < 4; w++)
            out[(ty * 4 + u) * 64 + tx * 4 + w] = acc[u][w];
}

// ---------------- QPsi[bi][h][e] = q_bi|h . Psi'[e]|h ----------------
__global__ void qpsi_kernel(const float* __restrict__ q, const float* __restrict__ Psi,
                            float* __restrict__ QPsi) {
    int bi = blockIdx.x;
    int t = threadIdx.x; // 64
    __shared__ float qs[HH];
    #pragma unroll
    for (int r = 0; r < 8; r++) qs[t + r * 64] = q[(size_t)bi * HH + t + r * 64];
    __syncthreads();
    int h = t >> 3, e = t & 7;
    float s = 0.f;
    #pragma unroll 8
    for (int d = 0; d < 64; d++) s += qs[h * 64 + d] * Psi[e * HH + h * 64 + d];
    QPsi[bi * 64 + t] = s;
}

// ---------------- attention ----------------
__global__ __launch_bounds__(256) void attn_kernel(const float* __restrict__ QD,
                                                   const float* __restrict__ QPsi,
                                                   const float* __restrict__ v,
                                                   const int* __restrict__ adj,
                                                   const float* __restrict__ p0,
                                                   const float* __restrict__ pi,
                                                   const float* __restrict__ pj,
                                                   int T,
                                                   float* __restrict__ o) {
    int bi = blockIdx.x;
    int b = bi >> 6, i = bi & 63;
    int t = threadIdx.x;
    __shared__ float sl[HH];
    const int* adjrow = adj + bi * NN;

    #pragma unroll
    for (int rep = 0; rep < 2; rep++) {
        int p = t + rep * 256;
        int h = p >> 6, j = p & 63;
        int e = adjrow[j];
        float lg;
        if (e > 0) {
            int bij = bi * 64 + j;
            size_t base = ((size_t)(b * 8 + h) * 64 + i) * 64;
            lg = QD[base + j];
            lg += p0[bij] * QPsi[(bi * 8 + h) * 8 + e];
            for (int tt = 0; tt < T; tt++) {
                const float* qd = QD + (size_t)(tt + 1) * 262144 + base;
                lg += pi[tt * NE + bij] * qd[i] + pj[tt * NE + bij] * qd[j];
            }
            lg *= INV_SCALE;
        } else {
            lg = -INFINITY;
        }
        sl[p] = lg;
    }
    __syncthreads();

    int w = t >> 5, lane = t & 31;
    float x0 = sl[w * 64 + lane], x1 = sl[w * 64 + lane + 32];
    float m = fmaxf(x0, x1);
    #pragma unroll
    for (int off = 16; off > 0; off >>= 1) m = fmaxf(m, __shfl_xor_sync(0xffffffffu, m, off));
    float e0 = expf(x0 - m), e1 = expf(x1 - m);
    float se = warpReduceSum(e0 + e1);
    float inv = 1.f / se;
    sl[w * 64 + lane] = e0 * inv;
    sl[w * 64 + lane + 32] = e1 * inv;
    __syncthreads();

    #pragma unroll
    for (int rep = 0; rep < 2; rep++) {
        int p = t + rep * 256;
        int h = p >> 6, d = p & 63;
        float s = 0.f;
        #pragma unroll 8
        for (int j = 0; j < 64; j++)
            s += sl[h * 64 + j] * v[(size_t)(b * 64 + j) * HH + h * 64 + d];
        o[(size_t)bi * HH + p] = s;
    }
}

// ---------------- batched [64,64] Gram over 512 ----------------
struct DJob { const float* A; const float* B; float* C; };
struct DParams { DJob jobs[6]; int n; };
__global__ __launch_bounds__(256) void gram_kernel(DParams P) {
    DJob job = P.jobs[blockIdx.x];
    int b = blockIdx.y;
    __shared__ float As[64][33];
    __shared__ float Bs2[64][33];
    int tid = threadIdx.x;
    int tx = tid & 15, ty = tid >> 4;
    float acc[4][4];
    #pragma unroll
    for (int u = 0; u < 4; u++)
        #pragma unroll
        for (int w = 0; w < 4; w++) acc[u][w] = 0.f;

    for (int kc = 0; kc < 16; kc++) {
        #pragma unroll
        for (int r = 0; r < 8; r++) {
            int idx = tid + r * 256;
            int n = idx >> 5, kk = idx & 31;
            As[n][kk] = job.A[(size_t)(b * 64 + n) * HH + kc * 32 + kk];
            Bs2[n][kk] = job.B[(size_t)(b * 64 + n) * HH + kc * 32 + kk];
        }
        __syncthreads();
        #pragma unroll 8
        for (int kk = 0; kk < 32; kk++) {
            float a0 = As[ty * 4 + 0][kk], a1 = As[ty * 4 + 1][kk];
            float a2 = As[ty * 4 + 2][kk], a3 = As[ty * 4 + 3][kk];
            float b0 = Bs2[tx * 4 + 0][kk], b1 = Bs2[tx * 4 + 1][kk];
            float b2 = Bs2[tx * 4 + 2][kk], b3 = Bs2[tx * 4 + 3][kk];
            acc[0][0] += a0 * b0; acc[0][1] += a0 * b1; acc[0][2] += a0 * b2; acc[0][3] += a0 * b3;
            acc[1][0] += a1 * b0; acc[1][1] += a1 * b1; acc[1][2] += a1 * b2; acc[1][3] += a1 * b3;
            acc[2][0] += a2 * b0; acc[2][1] += a2 * b1; acc[2][2] += a2 * b2; acc[2][3] += a2 * b3;
            acc[3][0] += a3 * b0; acc[3][1] += a3 * b1; acc[3][2] += a3 * b2; acc[3][3] += a3 * b3;
        }
        __syncthreads();
    }
    float* out = job.C + (size_t)b * 4096;
    #pragma unroll
    for (int u = 0; u < 4; u++)
        #pragma unroll
        for (int w = 0; w < 4; w++)
            out[(ty * 4 + u) * 64 + tx * 4 + w] = acc[u][w];
}

// ---------------- psidot ----------------
struct PJob { const float* A; float* C; int rows; };
struct PParams { PJob jobs[5]; int n; };
__global__ void psidot_kernel(PParams P, const float* __restrict__ Psi) {
    PJob job = P.jobs[blockIdx.x];
    int row = blockIdx.y;
    if (row >= job.rows) return;
    int t = threadIdx.x; // 256
    int w = t >> 5, lane = t & 31;
    float s = 0.f;
    #pragma unroll
    for (int u = 0; u < 16; u++) {
        int d = lane + u * 32;
        s += job.A[(size_t)row * HH + d] * Psi[w * HH + d];
    }
    s = warpReduceSum(s);
    if (lane == 0) job.C[row * 8 + w] = s;
}

// ---------------- edge coefficient update ----------------
__global__ void edge_kernel(const int* __restrict__ adj,
                            const float* __restrict__ PsiGram,
                            const float* __restrict__ PV,
                            const float* __restrict__ PX,
                            const float* __restrict__ G,
                            const float* __restrict__ VX,
                            float* __restrict__ p0,
                            float* __restrict__ pi,
                            float* __restrict__ pj,
                            int T) {
    int bij = blockIdx.x * blockDim.x + threadIdx.x; // 32768
    int b = bij >> 12;
    int ij = bij & 4095;
    int i = ij >> 6, j = ij & 63;
    int e = adj[bij];
    int ni = b * 64 + i, nj = b * 64 + j;

    float P0 = p0[bij];
    float s = P0 * P0 * PsiGram[e * 8 + e];
    float a0 = P0 * PX[ni * 8 + e];
    float a1 = P0 * PX[nj * 8 + e];

    float ci[3], cj[3];
    for (int t = 0; t < T; t++) { ci[t] = pi[t * NE + bij]; cj[t] = pj[t * NE + bij]; }

    for (int t = 0; t < T; t++) {
        s += 2.f * P0 * (ci[t] * PV[t * (ROWS * 8) + ni * 8 + e] +
                         cj[t] * PV[t * (ROWS * 8) + nj * 8 + e]);
        const float* vx = VX + (size_t)t * NE + (size_t)b * 4096;
        a0 += ci[t] * vx[i * 64 + i] + cj[t] * vx[j * 64 + i];
        a1 += ci[t] * vx[i * 64 + j] + cj[t] * vx[j * 64 + j];
        for (int ss2 = 0; ss2 < T; ss2++) {
            const float* g = G + (size_t)(ss2 * 3 + t) * NE + (size_t)b * 4096;
            s += ci[ss2] * ci[t] * g[i * 64 + i]
               + cj[ss2] * cj[t] * g[j * 64 + j]
               + 2.f * ci[ss2] * cj[t] * g[i * 64 + j];
        }
    }

    float u0 = s * INV_SCALE, u1 = a0 * INV_SCALE, u2 = a1 * INV_SCALE;
    float mm = fmaxf(u0, fmaxf(u1, u2));
    float q0 = expf(u0 - mm), q1 = expf(u1 - mm), q2 = expf(u2 - mm);
    float inv = 1.f / (q0 + q1 + q2);
    float w0 = q0 * inv;

    p0[bij] = w0 * P0;
    for (int t = 0; t < T; t++) {
        pi[t * NE + bij] = w0 * ci[t];
        pj[t * NE + bij] = w0 * cj[t];
    }
    pi[T * NE + bij] = q1 * inv;
    pj[T * NE + bij] = q2 * inv;
}

// ---------------- head ----------------
__global__ __launch_bounds__(512) void head_kernel(const float* __restrict__ x,
                                                   const float* __restrict__ Wout,
                                                   const float* __restrict__ Wpred,
                                                   const float* __restrict__ bpred,
                                                   float* __restrict__ out) {
    int b = blockIdx.x;
    int t = threadIdx.x; // 512
    __shared__ float xb[HH];
    __shared__ float cvec[HH];
    __shared__ float r0[16], r1[16];
    xb[t] = x[(size_t)(b * NN) * HH + t];
    __syncthreads();
    float s = 0.f;
    #pragma unroll 8
    for (int h2 = 0; h2 < HH; h2++) s += xb[h2] * Wout[(size_t)h2 * HH + t];
    cvec[t] = tanhf(s);
    __syncthreads();
    float pr0 = cvec[t] * Wpred[t * 2 + 0];
    float pr1 = cvec[t] * Wpred[t * 2 + 1];
    pr0 = warpReduceSum(pr0);
    pr1 = warpReduceSum(pr1);
    int lane = t & 31, w = t >> 5;
    if (lane == 0) { r0[w] = pr0; r1[w] = pr1; }
    __syncthreads();
    if (t == 0) {
        float l0 = bpred[0], l1 = bpred[1];
        #pragma unroll
        for (int q2 = 0; q2 < 16; q2++) { l0 += r0[q2]; l1 += r1[q2]; }
        float m = fmaxf(l0, l1);
        float e0 = expf(l0 - m), e1 = expf(l1 - m);
        float inv = 1.f / (e0 + e1);
        out[b * 2 + 0] = e0 * inv;
        out[b * 2 + 1] = e1 * inv;
    }
}

// ---------------- orchestration ----------------
extern "C" void kernel_launch(void* const* d_in, const int* in_sizes, int n_in,
                              void* d_out, int out_size) {
    const int* input_batch = (const int*)d_in[0];
    const int* adj = (const int*)d_in[1];
    const float* atom_emb = (const float*)d_in[2];
    const float* bond_emb = (const float*)d_in[3];
    const float* Wq = (const float*)d_in[4];
    const float* Wk = (const float*)d_in[5];
    const float* Wv = (const float*)d_in[6];
    const float* Wew = (const float*)d_in[7];
    const float* Wstack = (const float*)d_in[8];
    const float* Wf1 = (const float*)d_in[9];
    const float* Wf2 = (const float*)d_in[10];
    const float* Wout = (const float*)d_in[11];
    const float* Wpred = (const float*)d_in[12];
    const float* bpred = (const float*)d_in[13];
    float* out = (float*)d_out;

    float *x, *xn, *q, *k, *v, *o, *resid, *h1, *ff, *Va, *Vb, *PsiA, *PsiB;
    float *p0, *pi, *pj, *QD, *QPsi, *PV, *PX, *PsiGram, *G, *VX;
    cudaGetSymbolAddress((void**)&x, g_x);
    cudaGetSymbolAddress((void**)&xn, g_xn);
    cudaGetSymbolAddress((void**)&q, g_q);
    cudaGetSymbolAddress((void**)&k, g_k);
    cudaGetSymbolAddress((void**)&v, g_v);
    cudaGetSymbolAddress((void**)&o, g_o);
    cudaGetSymbolAddress((void**)&resid, g_resid);
    cudaGetSymbolAddress((void**)&h1, g_h1);
    cudaGetSymbolAddress((void**)&ff, g_ff);
    cudaGetSymbolAddress((void**)&Va, g_Va);
    cudaGetSymbolAddress((void**)&Vb, g_Vb);
    cudaGetSymbolAddress((void**)&PsiA, g_PsiA);
    cudaGetSymbolAddress((void**)&PsiB, g_PsiB);
    cudaGetSymbolAddress((void**)&p0, g_p0);
    cudaGetSymbolAddress((void**)&pi, g_pi);
    cudaGetSymbolAddress((void**)&pj, g_pj);
    cudaGetSymbolAddress((void**)&QD, g_QD);
    cudaGetSymbolAddress((void**)&QPsi, g_QPsi);
    cudaGetSymbolAddress((void**)&PV, g_PV);
    cudaGetSymbolAddress((void**)&PX, g_PX);
    cudaGetSymbolAddress((void**)&PsiGram, g_PsiGram);
    cudaGetSymbolAddress((void**)&G, g_G);
    cudaGetSymbolAddress((void**)&VX, g_VX);

    embed_x_kernel<<<ROWS * HH / 256, 256>>>(input_batch, atom_emb, x);
    psi_copy_kernel<<<16, 256>>>(bond_emb, PsiA);
    initp0_kernel<<<NE / 256, 256>>>(p0);

    float* VbufA[3] = {Va, Va + ROWS * HH, Va + 2 * ROWS * HH};
    float* VbufB[3] = {Vb, Vb + ROWS * HH, Vb + 2 * ROWS * HH};
    float* prevDst[3] = {nullptr, nullptr, nullptr};

    for (int l = 0; l < NLAYERS; l++) {
        const float* Wq_l = Wq + (size_t)l * HH * HH;
        const float* Wk_l = Wk + (size_t)l * HH * HH;
        const float* Wv_l = Wv + (size_t)l * HH * HH;
        const float* Wew_l = Wew + (size_t)l * HH * HH;
        const float* Wst_l = Wstack + (size_t)l * HH * HH;
        const float* Wf1_l = Wf1 + (size_t)l * HH * FFD;
        const float* Wf2_l = Wf2 + (size_t)l * FFD * HH;

        int T = l;
        float** dst = (l & 1) ? VbufA : VbufB;
        const float* src[3];
        for (int t = 0; t < T - 1; t++) src[t] = prevDst[t];
        if (T > 0) src[T - 1] = x;
        float* psiSrc = (l & 1) ? PsiB : PsiA;
        float* psiDst = (l & 1) ? PsiA : PsiB;

        // 1) LN
        ln_kernel<<<ROWS, 256>>>(x, xn);

        // 2) fused GEMMs: q,k,v + V'_t + Psi'
        {
            GParams P;
            int nb = 0, blk = 0;
            auto add = [&](const float* A, const float* B2, const float* D2, float* C2,
                           int M, int N2, int K2, int mode) {
                P.jobs[nb] = {A, B2, D2, C2, M, N2, K2, mode, blk};
                blk += (M / 64) * (N2 / 64);
                nb++;
            };
            add(xn, Wq_l, nullptr, q, ROWS, HH, HH, 0);
            add(xn, Wk_l, nullptr, k, ROWS, HH, HH, 0);
            add(xn, Wv_l, nullptr, v, ROWS, HH, HH, 0);
            for (int t = 0; t < T; t++) add(src[t], Wew_l, nullptr, dst[t], ROWS, HH, HH, 0);
            add(psiSrc, Wew_l, nullptr, psiDst, 64, HH, HH, 0);
            P.nJobs = nb;
            gemm_tc_kernel<<<blk, 256>>>(P);
        }

        // 3) per-head einsums QD[0..T]
        {
            dim3 g(BB * NHEADS, 1 + T);
            qd_kernel<<<g, 256>>>(q, k, T > 0 ? dst[0] : nullptr,
                                  T > 1 ? dst[1] : nullptr, T > 2 ? dst[2] : nullptr, QD);
        }

        // 4) QPsi
        qpsi_kernel<<<ROWS, 64>>>(q, psiDst, QPsi);

        // 5) attention
        attn_kernel<<<ROWS, 256>>>(QD, QPsi, v, adj, p0, pi, pj, T, o);

        // 6) stack (+xn)
        {
            GParams P;
            P.jobs[0] = {o, Wst_l, xn, resid, ROWS, HH, HH, 1, 0};
            P.nJobs = 1;
            gemm_tc_kernel<<<(ROWS / 64) * (HH / 64), 256>>>(P);
        }

        // 7) LN
        ln_kernel<<<ROWS, 256>>>(resid, h1);

        // 8) FF1 (relu)
        {
            GParams P;
            P.jobs[0] = {h1, Wf1_l, nullptr, ff, ROWS, FFD, HH, 2, 0};
            P.nJobs = 1;
            gemm_tc_kernel<<<(ROWS / 64) * (FFD / 64), 256>>>(P);
        }
        // 9) FF2 (+resid) -> x
        {
            GParams P;
            P.jobs[0] = {ff, Wf2_l, resid, x, ROWS, HH, FFD, 1, 0};
            P.nJobs = 1;
            gemm_tc_kernel<<<(ROWS / 64) * (HH / 64), 256>>>(P);
        }

        if (l < NLAYERS - 1) {
            // 10) Gram matrices G[s,t] and VX[t]
            int nj = 0;
            DParams DP;
            for (int s = 0; s < T; s++)
                for (int t = 0; t < T; t++)
                    DP.jobs[nj++] = {dst[s], dst[t], G + (size_t)(s * 3 + t) * NE};
            for (int t = 0; t < T; t++)
                DP.jobs[nj++] = {dst[t], x, VX + (size_t)t * NE};
            DP.n = nj;
            if (nj > 0) {
                dim3 g(nj, BB);
                gram_kernel<<<g, 256>>>(DP);
            }

            // 11) psidot: PV_t, PX, PsiGram
            {
                PParams PP2;
                int np = 0;
                for (int t = 0; t < T; t++) PP2.jobs[np++] = {dst[t], PV + t * (ROWS * 8), ROWS};
                PP2.jobs[np++] = {x, PX, ROWS};
                PP2.jobs[np++] = {psiDst, PsiGram, 32};
                PP2.n = np;
                dim3 g(np, ROWS);
                psidot_kernel<<<g, 256>>>(PP2, psiDst);
            }

            // 12) edge coefficient update
            edge_kernel<<<NE / 256, 256>>>(adj, PsiGram, PV, PX, G, VX, p0, pi, pj, T);
        }

        prevDst[0] = dst[0]; prevDst[1] = dst[1]; prevDst[2] = dst[2];
    }

    head_kernel<<<BB, 512>>>(x, Wout, Wpred, bpred, out);
}

// round 5
// speedup vs baseline: 8.1526x; 1.3174x over previous
#include <cuda_runtime.h>
#include <math.h>
#include <stdint.h>

#define BB 8
#define NN 64
#define HH 512
#define NHEADS 8
#define SPD 64
#define NLAYERS 4
#define FFD 2048
#define NE 32768            // B*N*N edges
#define ROWS 512            // B*N
#define INV_SCALE 0.04419417382415922f  // 1/sqrt(512)

static __device__ __forceinline__ float warpReduceSum(float v) {
    #pragma unroll
    for (int o = 16; o > 0; o >>= 1) v += __shfl_xor_sync(0xffffffffu, v, o);
    return v;
}

static __device__ __forceinline__ uint32_t f2tf32(float f) {
    uint32_t u;
    asm("cvt.rna.tf32.f32 %0, %1;" : "=r"(u) : "f"(f));
    return u;
}

static __device__ __forceinline__ void mma_tf32(float* c, const uint32_t* a, const uint32_t* b) {
    asm volatile("mma.sync.aligned.m16n8k8.row.col.f32.tf32.tf32.f32 "
                 "{%0,%1,%2,%3}, {%4,%5,%6,%7}, {%8,%9}, {%0,%1,%2,%3};"
                 : "+f"(c[0]), "+f"(c[1]), "+f"(c[2]), "+f"(c[3])
                 : "r"(a[0]), "r"(a[1]), "r"(a[2]), "r"(a[3]), "r"(b[0]), "r"(b[1]));
}

static __device__ __forceinline__ void cpasync16(void* smem_dst, const void* gmem_src) {
    uint32_t d = (uint32_t)__cvta_generic_to_shared(smem_dst);
    asm volatile("cp.async.ca.shared.global [%0], [%1], 16;\n" :: "r"(d), "l"(gmem_src));
}

// ---------------- scratch (device globals; zero-init, no allocation) ----------------
__device__ __align__(128) float g_x[ROWS * HH];
__device__ __align__(128) float g_xn[ROWS * HH];
__device__ __align__(128) float g_q[ROWS * HH];
__device__ __align__(128) float g_k[ROWS * HH];
__device__ __align__(128) float g_v[ROWS * HH];
__device__ __align__(128) float g_o[ROWS * HH];
__device__ __align__(128) float g_resid[ROWS * HH];
__device__ __align__(128) float g_h1[ROWS * HH];
__device__ __align__(128) float g_ff[ROWS * FFD];
__device__ __align__(128) float g_Va[3 * ROWS * HH];
__device__ __align__(128) float g_Vb[3 * ROWS * HH];
__device__ __align__(128) float g_PsiA[64 * HH];   // rows 8..63 stay 0
__device__ __align__(128) float g_PsiB[64 * HH];
__device__ float g_p0[NE];
__device__ float g_pi[3 * NE];
__device__ float g_pj[3 * NE];
__device__ float g_QD[4 * BB * NHEADS * NN * NN];  // [src][b][h][i][j]
__device__ float g_PV[3 * ROWS * 8];               // [t][row][e]
__device__ float g_PX[ROWS * 8];                   // [row][e]
__device__ float g_PsiGram[64 * 8];                // rows 0..7 used
__device__ float g_G[9 * BB * NN * NN];            // [s*3+t][b][n][m]
__device__ float g_VX[3 * BB * NN * NN];           // [t][b][n][m]

// ---------------- fused init: embed x, copy psi, init p0 ----------------
__global__ void init_kernel(const int* __restrict__ ib, const float* __restrict__ aemb,
                            const float* __restrict__ bemb,
                            float* __restrict__ x, float* __restrict__ psi,
                            float* __restrict__ p0) {
    int idx = blockIdx.x * blockDim.x + threadIdx.x; // 262144
    int row = idx >> 9;
    int h = idx & 511;
    x[idx] = aemb[ib[row] * HH + h];
    if (idx < 4096) psi[idx] = bemb[idx];
    if (idx < NE) p0[idx] = 1.0f;
}

// ---------------- LayerNorm ----------------
__global__ void ln_kernel(const float* __restrict__ in, float* __restrict__ out) {
    __shared__ float sh[8];
    int row = blockIdx.x;
    int t = threadIdx.x; // 256
    const float* r = in + row * HH;
    float v0 = r[t], v1 = r[t + 256];
    int lane = t & 31, w = t >> 5;
    float s = warpReduceSum(v0 + v1);
    if (lane == 0) sh[w] = s;
    __syncthreads();
    if (w == 0) {
        float x = (lane < 8) ? sh[lane] : 0.f;
        x = warpReduceSum(x);
        if (lane == 0) sh[0] = x;
    }
    __syncthreads();
    float mean = sh[0] * (1.f / HH);
    __syncthreads();
    float d0 = v0 - mean, d1 = v1 - mean;
    float vs = warpReduceSum(d0 * d0 + d1 * d1);
    if (lane == 0) sh[w] = vs;
    __syncthreads();
    if (w == 0) {
        float x = (lane < 8) ? sh[lane] : 0.f;
        x = warpReduceSum(x);
        if (lane == 0) sh[0] = x;
    }
    __syncthreads();
    float rinv = rsqrtf(sh[0] * (1.f / HH) + 1e-5f);
    out[row * HH + t] = d0 * rinv;
    out[row * HH + t + 256] = d1 * rinv;
}

// ---------------- batched-job TF32 TC GEMM, cp.async double-buffered ----------------
// mode 0: C = AB ; 1: C = AB + D ; 2: C = relu(AB)
struct GJob {
    const float* A; const float* B; const float* D; float* C;
    int M, N, K, mode, blkStart;
};
struct GParams { GJob jobs[8]; int nJobs; };

__global__ __launch_bounds__(256) void gemm_tc_kernel(GParams P) {
    int bx = blockIdx.x;
    int jb = 0;
    #pragma unroll
    for (int t = 1; t < 8; t++)
        if (t < P.nJobs && bx >= P.jobs[t].blkStart) jb = t;
    GJob job = P.jobs[jb];
    int tile = bx - job.blkStart;
    int tilesN = job.N >> 6;
    int tm = tile / tilesN, tn = tile - tm * tilesN;
    int N = job.N, K = job.K;
    int rowBase = tm * 64, colBase = tn * 64;

    __shared__ float As[2][64][36];   // stride 36 (≡4 mod 32): frag reads conflict-free
    __shared__ float Bs[2][32][72];   // stride 72 (≡8 mod 32)

    int tid = threadIdx.x;
    int lane = tid & 31, wid = tid >> 5;
    int wm = wid >> 2;        // 0..1
    int wn = wid & 3;         // 0..3
    int g = lane >> 2, t4 = lane & 3;

    float acc[2][2][4];
    #pragma unroll
    for (int mf = 0; mf < 2; mf++)
        #pragma unroll
        for (int nf = 0; nf < 2; nf++)
            #pragma unroll
            for (int r = 0; r < 4; r++) acc[mf][nf][r] = 0.f;

    int arow = tid >> 3, ac4 = tid & 7;     // A: 64 rows x 8 float4-cols per 32-K chunk
    int brow = tid >> 4, bc4 = tid & 15;    // B: 32 rows x 16 float4-cols

    const float* Abase = job.A + (size_t)rowBase * K;
    const float* Bbase = job.B + colBase;

    int nk = K >> 5;
    // preload chunk 0
    {
        cpasync16(&As[0][arow][ac4 * 4], Abase + (size_t)arow * K + ac4 * 4);
        cpasync16(&As[0][arow + 32][ac4 * 4], Abase + (size_t)(arow + 32) * K + ac4 * 4);
        cpasync16(&Bs[0][brow][bc4 * 4], Bbase + (size_t)brow * N + bc4 * 4);
        cpasync16(&Bs[0][brow + 16][bc4 * 4], Bbase + (size_t)(brow + 16) * N + bc4 * 4);
        asm volatile("cp.async.commit_group;\n");
    }

    for (int i = 0; i < nk; i++) {
        if (i + 1 < nk) {
            int k0 = (i + 1) << 5;
            int st = (i + 1) & 1;
            cpasync16(&As[st][arow][ac4 * 4], Abase + (size_t)arow * K + k0 + ac4 * 4);
            cpasync16(&As[st][arow + 32][ac4 * 4], Abase + (size_t)(arow + 32) * K + k0 + ac4 * 4);
            cpasync16(&Bs[st][brow][bc4 * 4], Bbase + (size_t)(k0 + brow) * N + bc4 * 4);
            cpasync16(&Bs[st][brow + 16][bc4 * 4], Bbase + (size_t)(k0 + brow + 16) * N + bc4 * 4);
            asm volatile("cp.async.commit_group;\n");
            asm volatile("cp.async.wait_group 1;\n");
        } else {
            asm volatile("cp.async.wait_group 0;\n");
        }
        __syncthreads();
        int st = i & 1;
        #pragma unroll
        for (int ks = 0; ks < 4; ks++) {
            uint32_t a[2][4], b[2][2];
            #pragma unroll
            for (int mf = 0; mf < 2; mf++) {
                int r0 = wm * 32 + mf * 16;
                a[mf][0] = f2tf32(As[st][r0 + g][ks * 8 + t4]);
                a[mf][1] = f2tf32(As[st][r0 + 8 + g][ks * 8 + t4]);
                a[mf][2] = f2tf32(As[st][r0 + g][ks * 8 + t4 + 4]);
                a[mf][3] = f2tf32(As[st][r0 + 8 + g][ks * 8 + t4 + 4]);
            }
            #pragma unroll
            for (int nf = 0; nf < 2; nf++) {
                int c0 = wn * 16 + nf * 8;
                b[nf][0] = f2tf32(Bs[st][ks * 8 + t4][c0 + g]);
                b[nf][1] = f2tf32(Bs[st][ks * 8 + t4 + 4][c0 + g]);
            }
            #pragma unroll
            for (int mf = 0; mf < 2; mf++)
                #pragma unroll
                for (int nf = 0; nf < 2; nf++)
                    mma_tf32(acc[mf][nf], a[mf], b[nf]);
        }
        __syncthreads();
    }

    #pragma unroll
    for (int mf = 0; mf < 2; mf++) {
        #pragma unroll
        for (int nf = 0; nf < 2; nf++) {
            int colb = colBase + wn * 16 + nf * 8 + t4 * 2;
            #pragma unroll
            for (int half = 0; half < 2; half++) {
                int row = rowBase + wm * 32 + mf * 16 + g + half * 8;
                float vx = acc[mf][nf][half * 2 + 0];
                float vy = acc[mf][nf][half * 2 + 1];
                size_t off = (size_t)row * N + colb;
                if (job.mode == 1) {
                    vx += job.D[off];
                    vy += job.D[off + 1];
                } else if (job.mode == 2) {
                    vx = fmaxf(vx, 0.f);
                    vy = fmaxf(vy, 0.f);
                }
                *(float2*)&job.C[off] = make_float2(vx, vy);
            }
        }
    }
}

// ---------------- per-head [64,64] einsum: QD[src][b,h,i,j] = q_i|h . S_j|h ----------------
__global__ __launch_bounds__(256) void qd_kernel(const float* __restrict__ q,
                                                 const float* __restrict__ k,
                                                 const float* v0, const float* v1, const float* v2,
                                                 float* __restrict__ QD) {
    int bh = blockIdx.x;          // b*8+h
    int src = blockIdx.y;
    int b = bh >> 3, h = bh & 7;
    const float* S = (src == 0) ? k : (src == 1 ? v0 : (src == 2 ? v1 : v2));

    __shared__ float Qs[64][65];
    __shared__ float Ss[64][65];
    int tid = threadIdx.x;
    #pragma unroll
    for (int r = 0; r < 16; r++) {
        int idx = tid + r * 256;
        int i = idx >> 6, d = idx & 63;
        size_t gg = (size_t)(b * 64 + i) * HH + h * 64 + d;
        Qs[i][d] = q[gg];
        Ss[i][d] = S[gg];
    }
    __syncthreads();
    int tx = tid & 15, ty = tid >> 4;
    float acc[4][4];
    #pragma unroll
    for (int u = 0; u < 4; u++)
        #pragma unroll
        for (int w = 0; w < 4; w++) acc[u][w] = 0.f;
    #pragma unroll 4
    for (int d = 0; d < 64; d++) {
        float a0 = Qs[ty * 4 + 0][d], a1 = Qs[ty * 4 + 1][d];
        float a2 = Qs[ty * 4 + 2][d], a3 = Qs[ty * 4 + 3][d];
        float b0 = Ss[tx * 4 + 0][d], b1 = Ss[tx * 4 + 1][d];
        float b2 = Ss[tx * 4 + 2][d], b3 = Ss[tx * 4 + 3][d];
        acc[0][0] += a0 * b0; acc[0][1] += a0 * b1; acc[0][2] += a0 * b2; acc[0][3] += a0 * b3;
        acc[1][0] += a1 * b0; acc[1][1] += a1 * b1; acc[1][2] += a1 * b2; acc[1][3] += a1 * b3;
        acc[2][0] += a2 * b0; acc[2][1] += a2 * b1; acc[2][2] += a2 * b2; acc[2][3] += a2 * b3;
        acc[3][0] += a3 * b0; acc[3][1] += a3 * b1; acc[3][2] += a3 * b2; acc[3][3] += a3 * b3;
    }
    float* out = QD + ((size_t)src * 64 + bh) * 4096;
    #pragma unroll
    for (int u = 0; u < 4; u++)
        #pragma unroll
        for (int w = 0; w < 4; w++)
            out[(ty * 4 + u) * 64 + tx * 4 + w] = acc[u][w];
}

// ---------------- attention (with fused QPsi) ----------------
__global__ __launch_bounds__(256) void attn_kernel(const float* __restrict__ QD,
                                                   const float* __restrict__ Psi,
                                                   const float* __restrict__ q,
                                                   const float* __restrict__ v,
                                                   const int* __restrict__ adj,
                                                   const float* __restrict__ p0,
                                                   const float* __restrict__ pi,
                                                   const float* __restrict__ pj,
                                                   int T,
                                                   float* __restrict__ o) {
    int bi = blockIdx.x;
    int b = bi >> 6, i = bi & 63;
    int t = threadIdx.x;
    __shared__ float sl[HH];
    __shared__ float qrow[HH];
    __shared__ float qp[64];
    const int* adjrow = adj + bi * NN;

    qrow[t] = q[(size_t)bi * HH + t];
    qrow[t + 256] = q[(size_t)bi * HH + t + 256];
    __syncthreads();
    if (t < 64) {
        int h = t >> 3, e = t & 7;
        float s = 0.f;
        #pragma unroll 8
        for (int d = 0; d < 64; d++) s += qrow[h * 64 + d] * Psi[e * HH + h * 64 + d];
        qp[t] = s;
    }
    __syncthreads();

    #pragma unroll
    for (int rep = 0; rep < 2; rep++) {
        int p = t + rep * 256;
        int h = p >> 6, j = p & 63;
        int e = adjrow[j];
        float lg;
        if (e > 0) {
            int bij = bi * 64 + j;
            size_t base = ((size_t)(b * 8 + h) * 64 + i) * 64;
            lg = QD[base + j];
            lg += p0[bij] * qp[h * 8 + e];
            for (int tt = 0; tt < T; tt++) {
                const float* qd = QD + (size_t)(tt + 1) * 262144 + base;
                lg += pi[tt * NE + bij] * qd[i] + pj[tt * NE + bij] * qd[j];
            }
            lg *= INV_SCALE;
        } else {
            lg = -INFINITY;
        }
        sl[p] = lg;
    }
    __syncthreads();

    int w = t >> 5, lane = t & 31;
    float x0 = sl[w * 64 + lane], x1 = sl[w * 64 + lane + 32];
    float m = fmaxf(x0, x1);
    #pragma unroll
    for (int off = 16; off > 0; off >>= 1) m = fmaxf(m, __shfl_xor_sync(0xffffffffu, m, off));
    float e0 = expf(x0 - m), e1 = expf(x1 - m);
    float se = warpReduceSum(e0 + e1);
    float inv = 1.f / se;
    sl[w * 64 + lane] = e0 * inv;
    sl[w * 64 + lane + 32] = e1 * inv;
    __syncthreads();

    #pragma unroll
    for (int rep = 0; rep < 2; rep++) {
        int p = t + rep * 256;
        int h = p >> 6, d = p & 63;
        float s = 0.f;
        #pragma unroll 8
        for (int j = 0; j < 64; j++)
            s += sl[h * 64 + j] * v[(size_t)(b * 64 + j) * HH + h * 64 + d];
        o[(size_t)bi * HH + p] = s;
    }
}

// ---------------- batched [64,64] Gram over 512 ----------------
struct DJob { const float* A; const float* B; float* C; };
struct DParams { DJob jobs[6]; int n; };
__global__ __launch_bounds__(256) void gram_kernel(DParams P) {
    DJob job = P.jobs[blockIdx.x];
    int b = blockIdx.y;
    __shared__ float As[64][33];
    __shared__ float Bs2[64][33];
    int tid = threadIdx.x;
    int tx = tid & 15, ty = tid >> 4;
    float acc[4][4];
    #pragma unroll
    for (int u = 0; u < 4; u++)
        #pragma unroll
        for (int w = 0; w < 4; w++) acc[u][w] = 0.f;

    for (int kc = 0; kc < 16; kc++) {
        #pragma unroll
        for (int r = 0; r < 8; r++) {
            int idx = tid + r * 256;
            int n = idx >> 5, kk = idx & 31;
            As[n][kk] = job.A[(size_t)(b * 64 + n) * HH + kc * 32 + kk];
            Bs2[n][kk] = job.B[(size_t)(b * 64 + n) * HH + kc * 32 + kk];
        }
        __syncthreads();
        #pragma unroll 8
        for (int kk = 0; kk < 32; kk++) {
            float a0 = As[ty * 4 + 0][kk], a1 = As[ty * 4 + 1][kk];
            float a2 = As[ty * 4 + 2][kk], a3 = As[ty * 4 + 3][kk];
            float b0 = Bs2[tx * 4 + 0][kk], b1 = Bs2[tx * 4 + 1][kk];
            float b2 = Bs2[tx * 4 + 2][kk], b3 = Bs2[tx * 4 + 3][kk];
            acc[0][0] += a0 * b0; acc[0][1] += a0 * b1; acc[0][2] += a0 * b2; acc[0][3] += a0 * b3;
            acc[1][0] += a1 * b0; acc[1][1] += a1 * b1; acc[1][2] += a1 * b2; acc[1][3] += a1 * b3;
            acc[2][0] += a2 * b0; acc[2][1] += a2 * b1; acc[2][2] += a2 * b2; acc[2][3] += a2 * b3;
            acc[3][0] += a3 * b0; acc[3][1] += a3 * b1; acc[3][2] += a3 * b2; acc[3][3] += a3 * b3;
        }
        __syncthreads();
    }
    float* out = job.C + (size_t)b * 4096;
    #pragma unroll
    for (int u = 0; u < 4; u++)
        #pragma unroll
        for (int w = 0; w < 4; w++)
            out[(ty * 4 + u) * 64 + tx * 4 + w] = acc[u][w];
}

// ---------------- psidot ----------------
struct PJob { const float* A; float* C; int rows; };
struct PParams { PJob jobs[5]; int n; };
__global__ void psidot_kernel(PParams P, const float* __restrict__ Psi) {
    PJob job = P.jobs[blockIdx.x];
    int row = blockIdx.y;
    if (row >= job.rows) return;
    int t = threadIdx.x; // 256
    int w = t >> 5, lane = t & 31;
    float s = 0.f;
    #pragma unroll
    for (int u = 0; u < 16; u++) {
        int d = lane + u * 32;
        s += job.A[(size_t)row * HH + d] * Psi[w * HH + d];
    }
    s = warpReduceSum(s);
    if (lane == 0) job.C[row * 8 + w] = s;
}

// ---------------- edge coefficient update ----------------
__global__ void edge_kernel(const int* __restrict__ adj,
                            const float* __restrict__ PsiGram,
                            const float* __restrict__ PV,
                            const float* __restrict__ PX,
                            const float* __restrict__ G,
                            const float* __restrict__ VX,
                            float* __restrict__ p0,
                            float* __restrict__ pi,
                            float* __restrict__ pj,
                            int T) {
    int bij = blockIdx.x * blockDim.x + threadIdx.x; // 32768
    int b = bij >> 12;
    int ij = bij & 4095;
    int i = ij >> 6, j = ij & 63;
    int e = adj[bij];
    int ni = b * 64 + i, nj = b * 64 + j;

    float P0 = p0[bij];
    float s = P0 * P0 * PsiGram[e * 8 + e];
    float a0 = P0 * PX[ni * 8 + e];
    float a1 = P0 * PX[nj * 8 + e];

    float ci[3], cj[3];
    for (int t = 0; t < T; t++) { ci[t] = pi[t * NE + bij]; cj[t] = pj[t * NE + bij]; }

    for (int t = 0; t < T; t++) {
        s += 2.f * P0 * (ci[t] * PV[t * (ROWS * 8) + ni * 8 + e] +
                         cj[t] * PV[t * (ROWS * 8) + nj * 8 + e]);
        const float* vx = VX + (size_t)t * NE + (size_t)b * 4096;
        a0 += ci[t] * vx[i * 64 + i] + cj[t] * vx[j * 64 + i];
        a1 += ci[t] * vx[i * 64 + j] + cj[t] * vx[j * 64 + j];
        for (int ss2 = 0; ss2 < T; ss2++) {
            const float* g = G + (size_t)(ss2 * 3 + t) * NE + (size_t)b * 4096;
            s += ci[ss2] * ci[t] * g[i * 64 + i]
               + cj[ss2] * cj[t] * g[j * 64 + j]
               + 2.f * ci[ss2] * cj[t] * g[i * 64 + j];
        }
    }

    float u0 = s * INV_SCALE, u1 = a0 * INV_SCALE, u2 = a1 * INV_SCALE;
    float mm = fmaxf(u0, fmaxf(u1, u2));
    float q0 = expf(u0 - mm), q1 = expf(u1 - mm), q2 = expf(u2 - mm);
    float inv = 1.f / (q0 + q1 + q2);
    float w0 = q0 * inv;

    p0[bij] = w0 * P0;
    for (int t = 0; t < T; t++) {
        pi[t * NE + bij] = w0 * ci[t];
        pj[t * NE + bij] = w0 * cj[t];
    }
    pi[T * NE + bij] = q1 * inv;
    pj[T * NE + bij] = q2 * inv;
}

// ---------------- head ----------------
__global__ __launch_bounds__(512) void head_kernel(const float* __restrict__ x,
                                                   const float* __restrict__ Wout,
                                                   const float* __restrict__ Wpred,
                                                   const float* __restrict__ bpred,
                                                   float* __restrict__ out) {
    int b = blockIdx.x;
    int t = threadIdx.x; // 512
    __shared__ float xb[HH];
    __shared__ float cvec[HH];
    __shared__ float r0[16], r1[16];
    xb[t] = x[(size_t)(b * NN) * HH + t];
    __syncthreads();
    float s = 0.f;
    #pragma unroll 8
    for (int h2 = 0; h2 < HH; h2++) s += xb[h2] * Wout[(size_t)h2 * HH + t];
    cvec[t] = tanhf(s);
    __syncthreads();
    float pr0 = cvec[t] * Wpred[t * 2 + 0];
    float pr1 = cvec[t] * Wpred[t * 2 + 1];
    pr0 = warpReduceSum(pr0);
    pr1 = warpReduceSum(pr1);
    int lane = t & 31, w = t >> 5;
    if (lane == 0) { r0[w] = pr0; r1[w] = pr1; }
    __syncthreads();
    if (t == 0) {
        float l0 = bpred[0], l1 = bpred[1];
        #pragma unroll
        for (int q2 = 0; q2 < 16; q2++) { l0 += r0[q2]; l1 += r1[q2]; }
        float m = fmaxf(l0, l1);
        float e0 = expf(l0 - m), e1 = expf(l1 - m);
        float inv = 1.f / (e0 + e1);
        out[b * 2 + 0] = e0 * inv;
        out[b * 2 + 1] = e1 * inv;
    }
}

// ---------------- orchestration ----------------
extern "C" void kernel_launch(void* const* d_in, const int* in_sizes, int n_in,
                              void* d_out, int out_size) {
    const int* input_batch = (const int*)d_in[0];
    const int* adj = (const int*)d_in[1];
    const float* atom_emb = (const float*)d_in[2];
    const float* bond_emb = (const float*)d_in[3];
    const float* Wq = (const float*)d_in[4];
    const float* Wk = (const float*)d_in[5];
    const float* Wv = (const float*)d_in[6];
    const float* Wew = (const float*)d_in[7];
    const float* Wstack = (const float*)d_in[8];
    const float* Wf1 = (const float*)d_in[9];
    const float* Wf2 = (const float*)d_in[10];
    const float* Wout = (const float*)d_in[11];
    const float* Wpred = (const float*)d_in[12];
    const float* bpred = (const float*)d_in[13];
    float* out = (float*)d_out;

    float *x, *xn, *q, *k, *v, *o, *resid, *h1, *ff, *Va, *Vb, *PsiA, *PsiB;
    float *p0, *pi, *pj, *QD, *PV, *PX, *PsiGram, *G, *VX;
    cudaGetSymbolAddress((void**)&x, g_x);
    cudaGetSymbolAddress((void**)&xn, g_xn);
    cudaGetSymbolAddress((void**)&q, g_q);
    cudaGetSymbolAddress((void**)&k, g_k);
    cudaGetSymbolAddress((void**)&v, g_v);
    cudaGetSymbolAddress((void**)&o, g_o);
    cudaGetSymbolAddress((void**)&resid, g_resid);
    cudaGetSymbolAddress((void**)&h1, g_h1);
    cudaGetSymbolAddress((void**)&ff, g_ff);
    cudaGetSymbolAddress((void**)&Va, g_Va);
    cudaGetSymbolAddress((void**)&Vb, g_Vb);
    cudaGetSymbolAddress((void**)&PsiA, g_PsiA);
    cudaGetSymbolAddress((void**)&PsiB, g_PsiB);
    cudaGetSymbolAddress((void**)&p0, g_p0);
    cudaGetSymbolAddress((void**)&pi, g_pi);
    cudaGetSymbolAddress((void**)&pj, g_pj);
    cudaGetSymbolAddress((void**)&QD, g_QD);
    cudaGetSymbolAddress((void**)&PV, g_PV);
    cudaGetSymbolAddress((void**)&PX, g_PX);
    cudaGetSymbolAddress((void**)&PsiGram, g_PsiGram);
    cudaGetSymbolAddress((void**)&G, g_G);
    cudaGetSymbolAddress((void**)&VX, g_VX);

    init_kernel<<<ROWS * HH / 256, 256>>>(input_batch, atom_emb, bond_emb, x, PsiA, p0);

    float* VbufA[3] = {Va, Va + ROWS * HH, Va + 2 * ROWS * HH};
    float* VbufB[3] = {Vb, Vb + ROWS * HH, Vb + 2 * ROWS * HH};
    float* prevDst[3] = {nullptr, nullptr, nullptr};

    for (int l = 0; l < NLAYERS; l++) {
        const float* Wq_l = Wq + (size_t)l * HH * HH;
        const float* Wk_l = Wk + (size_t)l * HH * HH;
        const float* Wv_l = Wv + (size_t)l * HH * HH;
        const float* Wew_l = Wew + (size_t)l * HH * HH;
        const float* Wst_l = Wstack + (size_t)l * HH * HH;
        const float* Wf1_l = Wf1 + (size_t)l * HH * FFD;
        const float* Wf2_l = Wf2 + (size_t)l * FFD * HH;

        int T = l;
        float** dst = (l & 1) ? VbufA : VbufB;
        const float* src[3];
        for (int t = 0; t < T - 1; t++) src[t] = prevDst[t];
        if (T > 0) src[T - 1] = x;
        float* psiSrc = (l & 1) ? PsiB : PsiA;
        float* psiDst = (l & 1) ? PsiA : PsiB;

        // 1) LN
        ln_kernel<<<ROWS, 256>>>(x, xn);

        // 2) fused GEMMs: q,k,v + V'_t + Psi'
        {
            GParams P;
            int nb = 0, blk = 0;
            auto add = [&](const float* A, const float* B2, const float* D2, float* C2,
                           int M, int N2, int K2, int mode) {
                P.jobs[nb] = {A, B2, D2, C2, M, N2, K2, mode, blk};
                blk += (M / 64) * (N2 / 64);
                nb++;
            };
            add(xn, Wq_l, nullptr, q, ROWS, HH, HH, 0);
            add(xn, Wk_l, nullptr, k, ROWS, HH, HH, 0);
            add(xn, Wv_l, nullptr, v, ROWS, HH, HH, 0);
            for (int t = 0; t < T; t++) add(src[t], Wew_l, nullptr, dst[t], ROWS, HH, HH, 0);
            add(psiSrc, Wew_l, nullptr, psiDst, 64, HH, HH, 0);
            P.nJobs = nb;
            gemm_tc_kernel<<<blk, 256>>>(P);
        }

        // 3) per-head einsums QD[0..T]
        {
            dim3 g(BB * NHEADS, 1 + T);
            qd_kernel<<<g, 256>>>(q, k, T > 0 ? dst[0] : nullptr,
                                  T > 1 ? dst[1] : nullptr, T > 2 ? dst[2] : nullptr, QD);
        }

        // 4) attention (with fused QPsi)
        attn_kernel<<<ROWS, 256>>>(QD, psiDst, q, v, adj, p0, pi, pj, T, o);

        // 5) stack (+xn)
        {
            GParams P;
            P.jobs[0] = {o, Wst_l, xn, resid, ROWS, HH, HH, 1, 0};
            P.nJobs = 1;
            gemm_tc_kernel<<<(ROWS / 64) * (HH / 64), 256>>>(P);
        }

        // 6) LN
        ln_kernel<<<ROWS, 256>>>(resid, h1);

        // 7) FF1 (relu)
        {
            GParams P;
            P.jobs[0] = {h1, Wf1_l, nullptr, ff, ROWS, FFD, HH, 2, 0};
            P.nJobs = 1;
            gemm_tc_kernel<<<(ROWS / 64) * (FFD / 64), 256>>>(P);
        }
        // 8) FF2 (+resid) -> x
        {
            GParams P;
            P.jobs[0] = {ff, Wf2_l, resid, x, ROWS, HH, FFD, 1, 0};
            P.nJobs = 1;
            gemm_tc_kernel<<<(ROWS / 64) * (HH / 64), 256>>>(P);
        }

        if (l < NLAYERS - 1) {
            // 9) Gram matrices G[s,t] and VX[t]
            int nj = 0;
            DParams DP;
            for (int s = 0; s < T; s++)
                for (int t = 0; t < T; t++)
                    DP.jobs[nj++] = {dst[s], dst[t], G + (size_t)(s * 3 + t) * NE};
            for (int t = 0; t < T; t++)
                DP.jobs[nj++] = {dst[t], x, VX + (size_t)t * NE};
            DP.n = nj;
            if (nj > 0) {
                dim3 g(nj, BB);
                gram_kernel<<<g, 256>>>(DP);
            }

            // 10) psidot: PV_t, PX, PsiGram
            {
                PParams PP2;
                int np = 0;
                for (int t = 0; t < T; t++) PP2.jobs[np++] = {dst[t], PV + t * (ROWS * 8), ROWS};
                PP2.jobs[np++] = {x, PX, ROWS};
                PP2.jobs[np++] = {psiDst, PsiGram, 32};
                PP2.n = np;
                dim3 g(np, ROWS);
                psidot_kernel<<<g, 256>>>(PP2, psiDst);
            }

            // 11) edge coefficient update
            edge_kernel<<<NE / 256, 256>>>(adj, PsiGram, PV, PX, G, VX, p0, pi, pj, T);
        }

        prevDst[0] = dst[0]; prevDst[1] = dst[1]; prevDst[2] = dst[2];
    }

    head_kernel<<<BB, 512>>>(x, Wout, Wpred, bpred, out);
}

// round 6
// speedup vs baseline: 11.4385x; 1.4031x over previous
#include <cuda_runtime.h>
#include <math.h>
#include <stdint.h>

#define BB 8
#define NN 64
#define HH 512
#define NHEADS 8
#define NLAYERS 4
#define FFD 2048
#define NE 32768            // B*N*N edges
#define ROWS 512            // B*N
#define INV_SCALE 0.04419417382415922f  // 1/sqrt(512)

static __device__ __forceinline__ float warpReduceSum(float v) {
    #pragma unroll
    for (int o = 16; o > 0; o >>= 1) v += __shfl_xor_sync(0xffffffffu, v, o);
    return v;
}

static __device__ __forceinline__ uint32_t f2tf32(float f) {
    uint32_t u;
    asm("cvt.rna.tf32.f32 %0, %1;" : "=r"(u) : "f"(f));
    return u;
}

static __device__ __forceinline__ void mma_tf32(float* c, const uint32_t* a, const uint32_t* b) {
    asm volatile("mma.sync.aligned.m16n8k8.row.col.f32.tf32.tf32.f32 "
                 "{%0,%1,%2,%3}, {%4,%5,%6,%7}, {%8,%9}, {%0,%1,%2,%3};"
                 : "+f"(c[0]), "+f"(c[1]), "+f"(c[2]), "+f"(c[3])
                 : "r"(a[0]), "r"(a[1]), "r"(a[2]), "r"(a[3]), "r"(b[0]), "r"(b[1]));
}

static __device__ __forceinline__ void cpasync16(void* smem_dst, const void* gmem_src) {
    uint32_t d = (uint32_t)__cvta_generic_to_shared(smem_dst);
    asm volatile("cp.async.ca.shared.global [%0], [%1], 16;\n" :: "r"(d), "l"(gmem_src));
}

// MMA pass over 64-deep contraction: A [64 rows][lda] row-major, B smem [k][ldb].
// Warp tile 32x16 (wm in 0..1, wn in 0..3). Accumulates into acc[2][2][4].
static __device__ __forceinline__ void mma_pass64(const float* A, int lda,
                                                  const float* Bsm, int ldb,
                                                  float acc[2][2][4]) {
    int tid = threadIdx.x;
    int lane = tid & 31, wid = tid >> 5;
    int wm = wid >> 2, wn = wid & 3;
    int g = lane >> 2, t4 = lane & 3;
    #pragma unroll
    for (int ks = 0; ks < 8; ks++) {
        uint32_t a[2][4], b[2][2];
        #pragma unroll
        for (int mf = 0; mf < 2; mf++) {
            int r0 = wm * 32 + mf * 16;
            a[mf][0] = f2tf32(A[(r0 + g) * lda + ks * 8 + t4]);
            a[mf][1] = f2tf32(A[(r0 + 8 + g) * lda + ks * 8 + t4]);
            a[mf][2] = f2tf32(A[(r0 + g) * lda + ks * 8 + t4 + 4]);
            a[mf][3] = f2tf32(A[(r0 + 8 + g) * lda + ks * 8 + t4 + 4]);
        }
        #pragma unroll
        for (int nf = 0; nf < 2; nf++) {
            int c0 = wn * 16 + nf * 8;
            b[nf][0] = f2tf32(Bsm[(ks * 8 + t4) * ldb + c0 + g]);
            b[nf][1] = f2tf32(Bsm[(ks * 8 + t4 + 4) * ldb + c0 + g]);
        }
        #pragma unroll
        for (int mf = 0; mf < 2; mf++)
            #pragma unroll
            for (int nf = 0; nf < 2; nf++)
                mma_tf32(acc[mf][nf], a[mf], b[nf]);
    }
}

// ---------------- scratch (device globals; zero-init, no allocation) ----------------
__device__ __align__(128) float g_x[ROWS * HH];
__device__ __align__(128) float g_xn[ROWS * HH];
__device__ __align__(128) float g_q[ROWS * HH];
__device__ __align__(128) float g_k[ROWS * HH];
__device__ __align__(128) float g_v[ROWS * HH];
__device__ __align__(128) float g_o[ROWS * HH];
__device__ __align__(128) float g_resid[ROWS * HH];
__device__ __align__(128) float g_h1[ROWS * HH];
__device__ __align__(128) float g_ff[ROWS * FFD];
__device__ __align__(128) float g_part[4 * ROWS * HH];   // split-K partials
__device__ __align__(128) float g_Va[3 * ROWS * HH];
__device__ __align__(128) float g_Vb[3 * ROWS * HH];
__device__ __align__(128) float g_PsiA[64 * HH];   // rows 8..63 stay 0
__device__ __align__(128) float g_PsiB[64 * HH];
__device__ float g_p0[NE];
__device__ float g_pi[3 * NE];
__device__ float g_pj[3 * NE];
__device__ float g_PV[3 * ROWS * 8];               // [t][row][e]
__device__ float g_PX[ROWS * 8];                   // [row][e]
__device__ float g_PsiGram[64 * 8];                // rows 0..7 used
__device__ float g_G[9 * BB * NN * NN];            // [s*3+t][b][n][m]
__device__ float g_VX[3 * BB * NN * NN];           // [t][b][n][m]

// ---------------- fused init: embed x, copy psi, init p0 ----------------
__global__ void init_kernel(const int* __restrict__ ib, const float* __restrict__ aemb,
                            const float* __restrict__ bemb,
                            float* __restrict__ x, float* __restrict__ psi,
                            float* __restrict__ p0) {
    int idx = blockIdx.x * blockDim.x + threadIdx.x; // 262144
    int row = idx >> 9;
    int h = idx & 511;
    x[idx] = aemb[ib[row] * HH + h];
    if (idx < 4096) psi[idx] = bemb[idx];
    if (idx < NE) p0[idx] = 1.0f;
}

// ---------------- LayerNorm ----------------
__global__ void ln_kernel(const float* __restrict__ in, float* __restrict__ out) {
    __shared__ float sh[8];
    int row = blockIdx.x;
    int t = threadIdx.x; // 256
    const float* r = in + row * HH;
    float v0 = r[t], v1 = r[t + 256];
    int lane = t & 31, w = t >> 5;
    float s = warpReduceSum(v0 + v1);
    if (lane == 0) sh[w] = s;
    __syncthreads();
    if (w == 0) {
        float x = (lane < 8) ? sh[lane] : 0.f;
        x = warpReduceSum(x);
        if (lane == 0) sh[0] = x;
    }
    __syncthreads();
    float mean = sh[0] * (1.f / HH);
    __syncthreads();
    float d0 = v0 - mean, d1 = v1 - mean;
    float vs = warpReduceSum(d0 * d0 + d1 * d1);
    if (lane == 0) sh[w] = vs;
    __syncthreads();
    if (w == 0) {
        float x = (lane < 8) ? sh[lane] : 0.f;
        x = warpReduceSum(x);
        if (lane == 0) sh[0] = x;
    }
    __syncthreads();
    float rinv = rsqrtf(sh[0] * (1.f / HH) + 1e-5f);
    out[row * HH + t] = d0 * rinv;
    out[row * HH + t + 256] = d1 * rinv;
}

// ---------------- combine split-K partials + residual, then LayerNorm ----------------
// X = D + sum(P0..P{np-1}) ; XN = LN(X)
__global__ void ln_combine_kernel(const float* __restrict__ P0, const float* __restrict__ P1,
                                  const float* __restrict__ P2, const float* __restrict__ P3,
                                  const float* __restrict__ D,
                                  float* __restrict__ X, float* __restrict__ XN, int np) {
    __shared__ float sh[8];
    int row = blockIdx.x;
    int t = threadIdx.x; // 256
    size_t base = (size_t)row * HH;
    float v0 = D[base + t] + P0[base + t] + P1[base + t];
    float v1 = D[base + t + 256] + P0[base + t + 256] + P1[base + t + 256];
    if (np == 4) {
        v0 += P2[base + t] + P3[base + t];
        v1 += P2[base + t + 256] + P3[base + t + 256];
    }
    X[base + t] = v0;
    X[base + t + 256] = v1;

    int lane = t & 31, w = t >> 5;
    float s = warpReduceSum(v0 + v1);
    if (lane == 0) sh[w] = s;
    __syncthreads();
    if (w == 0) {
        float x = (lane < 8) ? sh[lane] : 0.f;
        x = warpReduceSum(x);
        if (lane == 0) sh[0] = x;
    }
    __syncthreads();
    float mean = sh[0] * (1.f / HH);
    __syncthreads();
    float d0 = v0 - mean, d1 = v1 - mean;
    float vs = warpReduceSum(d0 * d0 + d1 * d1);
    if (lane == 0) sh[w] = vs;
    __syncthreads();
    if (w == 0) {
        float x = (lane < 8) ? sh[lane] : 0.f;
        x = warpReduceSum(x);
        if (lane == 0) sh[0] = x;
    }
    __syncthreads();
    float rinv = rsqrtf(sh[0] * (1.f / HH) + 1e-5f);
    XN[base + t] = d0 * rinv;
    XN[base + t + 256] = d1 * rinv;
}

// ---------------- batched-job TF32 TC GEMM, cp.async double-buffered, split-K capable ----
// mode 0: C = AB ; 1: C = AB + D ; 2: C = relu(AB)
struct GJob {
    const float* A; const float* B; const float* D; float* C;
    int M, N, K, mode, blkStart, kStart, kCount;
};
struct GParams { GJob jobs[8]; int nJobs; };

__global__ __launch_bounds__(256) void gemm_tc_kernel(GParams P) {
    int bx = blockIdx.x;
    int jb = 0;
    #pragma unroll
    for (int t = 1; t < 8; t++)
        if (t < P.nJobs && bx >= P.jobs[t].blkStart) jb = t;
    GJob job = P.jobs[jb];
    int tile = bx - job.blkStart;
    int tilesN = job.N >> 6;
    int tm = tile / tilesN, tn = tile - tm * tilesN;
    int N = job.N, K = job.K;
    int rowBase = tm * 64, colBase = tn * 64;

    __shared__ float As[2][64][36];   // stride 36 (≡4 mod 32)
    __shared__ float Bs[2][32][72];   // stride 72 (≡8 mod 32)

    int tid = threadIdx.x;
    int lane = tid & 31, wid = tid >> 5;
    int wm = wid >> 2;
    int wn = wid & 3;
    int g = lane >> 2, t4 = lane & 3;

    float acc[2][2][4];
    #pragma unroll
    for (int mf = 0; mf < 2; mf++)
        #pragma unroll
        for (int nf = 0; nf < 2; nf++)
            #pragma unroll
            for (int r = 0; r < 4; r++) acc[mf][nf][r] = 0.f;

    int arow = tid >> 3, ac4 = tid & 7;
    int brow = tid >> 4, bc4 = tid & 15;

    const float* Abase = job.A + (size_t)rowBase * K + job.kStart;
    const float* Bbase = job.B + (size_t)job.kStart * N + colBase;

    int nk = job.kCount >> 5;
    {
        cpasync16(&As[0][arow][ac4 * 4], Abase + (size_t)arow * K + ac4 * 4);
        cpasync16(&As[0][arow + 32][ac4 * 4], Abase + (size_t)(arow + 32) * K + ac4 * 4);
        cpasync16(&Bs[0][brow][bc4 * 4], Bbase + (size_t)brow * N + bc4 * 4);
        cpasync16(&Bs[0][brow + 16][bc4 * 4], Bbase + (size_t)(brow + 16) * N + bc4 * 4);
        asm volatile("cp.async.commit_group;\n");
    }

    for (int i = 0; i < nk; i++) {
        if (i + 1 < nk) {
            int k0 = (i + 1) << 5;
            int st = (i + 1) & 1;
            cpasync16(&As[st][arow][ac4 * 4], Abase + (size_t)arow * K + k0 + ac4 * 4);
            cpasync16(&As[st][arow + 32][ac4 * 4], Abase + (size_t)(arow + 32) * K + k0 + ac4 * 4);
            cpasync16(&Bs[st][brow][bc4 * 4], Bbase + (size_t)(k0 + brow) * N + bc4 * 4);
            cpasync16(&Bs[st][brow + 16][bc4 * 4], Bbase + (size_t)(k0 + brow + 16) * N + bc4 * 4);
            asm volatile("cp.async.commit_group;\n");
            asm volatile("cp.async.wait_group 1;\n");
        } else {
            asm volatile("cp.async.wait_group 0;\n");
        }
        __syncthreads();
        int st = i & 1;
        #pragma unroll
        for (int ks = 0; ks < 4; ks++) {
            uint32_t a[2][4], b[2][2];
            #pragma unroll
            for (int mf = 0; mf < 2; mf++) {
                int r0 = wm * 32 + mf * 16;
                a[mf][0] = f2tf32(As[st][r0 + g][ks * 8 + t4]);
                a[mf][1] = f2tf32(As[st][r0 + 8 + g][ks * 8 + t4]);
                a[mf][2] = f2tf32(As[st][r0 + g][ks * 8 + t4 + 4]);
                a[mf][3] = f2tf32(As[st][r0 + 8 + g][ks * 8 + t4 + 4]);
            }
            #pragma unroll
            for (int nf = 0; nf < 2; nf++) {
                int c0 = wn * 16 + nf * 8;
                b[nf][0] = f2tf32(Bs[st][ks * 8 + t4][c0 + g]);
                b[nf][1] = f2tf32(Bs[st][ks * 8 + t4 + 4][c0 + g]);
            }
            #pragma unroll
            for (int mf = 0; mf < 2; mf++)
                #pragma unroll
                for (int nf = 0; nf < 2; nf++)
                    mma_tf32(acc[mf][nf], a[mf], b[nf]);
        }
        __syncthreads();
    }

    #pragma unroll
    for (int mf = 0; mf < 2; mf++) {
        #pragma unroll
        for (int nf = 0; nf < 2; nf++) {
            int colb = colBase + wn * 16 + nf * 8 + t4 * 2;
            #pragma unroll
            for (int half = 0; half < 2; half++) {
                int row = rowBase + wm * 32 + mf * 16 + g + half * 8;
                float vx = acc[mf][nf][half * 2 + 0];
                float vy = acc[mf][nf][half * 2 + 1];
                size_t off = (size_t)row * N + colb;
                if (job.mode == 1) {
                    vx += job.D[off];
                    vy += job.D[off + 1];
                } else if (job.mode == 2) {
                    vx = fmaxf(vx, 0.f);
                    vy = fmaxf(vy, 0.f);
                }
                *(float2*)&job.C[off] = make_float2(vx, vy);
            }
        }
    }
}

// ---------------- fused MMA attention: one CTA per (b,h) ----------------
__global__ __launch_bounds__(256) void attn_fused_kernel(
    const float* __restrict__ q, const float* __restrict__ k, const float* __restrict__ v,
    const float* __restrict__ s0, const float* __restrict__ s1, const float* __restrict__ s2,
    const float* __restrict__ Psi, const int* __restrict__ adj,
    const float* __restrict__ p0, const float* __restrict__ pi, const float* __restrict__ pj,
    int T, float* __restrict__ o) {
    __shared__ float Qs[64][68];   // Q [i][d]; later reused as logits/attn [i][j]
    __shared__ float Ss[64][72];   // operand B: [k][n]
    __shared__ float qps[64][8];
    __shared__ float diag[64];

    int bh = blockIdx.x;
    int b = bh >> 3, h = bh & 7;
    int tid = threadIdx.x;
    int lane = tid & 31, wid = tid >> 5;
    int wm = wid >> 2, wn = wid & 3;
    int g = lane >> 2, t4 = lane & 3;
    int rb = b * 64;

    // load Q [i][d]
    #pragma unroll
    for (int r = 0; r < 4; r++) {
        int idx = tid + r * 256;               // 1024 float4
        int i = idx >> 4, dg = idx & 15;
        float4 f = *(const float4*)&q[(size_t)(rb + i) * HH + h * 64 + dg * 4];
        *(float4*)&Qs[i][dg * 4] = f;
    }
    // load K^T into Ss [d][j]
    #pragma unroll
    for (int r = 0; r < 4; r++) {
        int idx = tid + r * 256;
        int j = idx & 63, dg = idx >> 6;       // dg 0..15
        float4 f = *(const float4*)&k[(size_t)(rb + j) * HH + h * 64 + dg * 4];
        Ss[dg * 4 + 0][j] = f.x;
        Ss[dg * 4 + 1][j] = f.y;
        Ss[dg * 4 + 2][j] = f.z;
        Ss[dg * 4 + 3][j] = f.w;
    }
    __syncthreads();

    // qps[i][e] = Q_i|h . Psi[e]|h
    #pragma unroll
    for (int r = 0; r < 2; r++) {
        int idx = tid + r * 256;
        int i = idx >> 3, e = idx & 7;
        float s = 0.f;
        #pragma unroll 8
        for (int d = 0; d < 64; d++) s += Qs[i][d] * Psi[e * HH + h * 64 + d];
        qps[i][e] = s;
    }

    // S0 = Q K^T (held in registers)
    float acc[2][2][4];
    #pragma unroll
    for (int mf = 0; mf < 2; mf++)
        #pragma unroll
        for (int nf = 0; nf < 2; nf++)
            #pragma unroll
            for (int r = 0; r < 4; r++) acc[mf][nf][r] = 0.f;
    mma_pass64(&Qs[0][0], 68, &Ss[0][0], 72, acc);

    // source passes
    for (int t = 0; t < T; t++) {
        const float* src = (t == 0) ? s0 : ((t == 1) ? s1 : s2);
        __syncthreads();   // everyone done reading Ss
        #pragma unroll
        for (int r = 0; r < 4; r++) {
            int idx = tid + r * 256;
            int j = idx & 63, dg = idx >> 6;
            float4 f = *(const float4*)&src[(size_t)(rb + j) * HH + h * 64 + dg * 4];
            Ss[dg * 4 + 0][j] = f.x;
            Ss[dg * 4 + 1][j] = f.y;
            Ss[dg * 4 + 2][j] = f.z;
            Ss[dg * 4 + 3][j] = f.w;
        }
        __syncthreads();
        float mt[2][2][4];
        #pragma unroll
        for (int mf = 0; mf < 2; mf++)
            #pragma unroll
            for (int nf = 0; nf < 2; nf++)
                #pragma unroll
                for (int r = 0; r < 4; r++) mt[mf][nf][r] = 0.f;
        mma_pass64(&Qs[0][0], 68, &Ss[0][0], 72, mt);
        // diagonal of M_t
        #pragma unroll
        for (int mf = 0; mf < 2; mf++)
            #pragma unroll
            for (int nf = 0; nf < 2; nf++)
                #pragma unroll
                for (int half = 0; half < 2; half++)
                    #pragma unroll
                    for (int cc = 0; cc < 2; cc++) {
                        int row = wm * 32 + mf * 16 + g + half * 8;
                        int col = wn * 16 + nf * 8 + t4 * 2 + cc;
                        if (row == col) diag[row] = mt[mf][nf][half * 2 + cc];
                    }
        __syncthreads();
        // acc += pi_t * diag[i] + pj_t * M_t[i][j]
        #pragma unroll
        for (int mf = 0; mf < 2; mf++)
            #pragma unroll
            for (int nf = 0; nf < 2; nf++)
                #pragma unroll
                for (int half = 0; half < 2; half++)
                    #pragma unroll
                    for (int cc = 0; cc < 2; cc++) {
                        int row = wm * 32 + mf * 16 + g + half * 8;
                        int col = wn * 16 + nf * 8 + t4 * 2 + cc;
                        int bij = (rb + row) * 64 + col;
                        acc[mf][nf][half * 2 + cc] += pi[t * NE + bij] * diag[row]
                                                    + pj[t * NE + bij] * mt[mf][nf][half * 2 + cc];
                    }
    }

    __syncthreads();   // Qs dead (as Q); reuse as logits buffer
    float* sl = &Qs[0][0];
    #pragma unroll
    for (int mf = 0; mf < 2; mf++)
        #pragma unroll
        for (int nf = 0; nf < 2; nf++)
            #pragma unroll
            for (int half = 0; half < 2; half++)
                #pragma unroll
                for (int cc = 0; cc < 2; cc++) {
                    int row = wm * 32 + mf * 16 + g + half * 8;
                    int col = wn * 16 + nf * 8 + t4 * 2 + cc;
                    int bij = (rb + row) * 64 + col;
                    int e = adj[bij];
                    float val;
                    if (e > 0)
                        val = (acc[mf][nf][half * 2 + cc] + p0[bij] * qps[row][e]) * INV_SCALE;
                    else
                        val = -INFINITY;
                    sl[row * 68 + col] = val;
                }
    __syncthreads();

    // softmax (warp w: rows w*8..w*8+7) and V load in parallel
    #pragma unroll
    for (int ri = 0; ri < 8; ri++) {
        int r = wid * 8 + ri;
        float x0 = sl[r * 68 + lane], x1 = sl[r * 68 + lane + 32];
        float m = fmaxf(x0, x1);
        #pragma unroll
        for (int off2 = 16; off2 > 0; off2 >>= 1) m = fmaxf(m, __shfl_xor_sync(0xffffffffu, m, off2));
        float e0 = expf(x0 - m), e1 = expf(x1 - m);
        float se = warpReduceSum(e0 + e1);
        float inv = 1.f / se;
        sl[r * 68 + lane] = e0 * inv;
        sl[r * 68 + lane + 32] = e1 * inv;
    }
    // load V direct [j][d] (contraction j rows)
    #pragma unroll
    for (int r = 0; r < 4; r++) {
        int idx = tid + r * 256;
        int j = idx >> 4, dg = idx & 15;
        float4 f = *(const float4*)&v[(size_t)(rb + j) * HH + h * 64 + dg * 4];
        *(float4*)&Ss[j][dg * 4] = f;
    }
    __syncthreads();

    // O = attn @ V
    float oacc[2][2][4];
    #pragma unroll
    for (int mf = 0; mf < 2; mf++)
        #pragma unroll
        for (int nf = 0; nf < 2; nf++)
            #pragma unroll
            for (int r = 0; r < 4; r++) oacc[mf][nf][r] = 0.f;
    mma_pass64(sl, 68, &Ss[0][0], 72, oacc);

    #pragma unroll
    for (int mf = 0; mf < 2; mf++)
        #pragma unroll
        for (int nf = 0; nf < 2; nf++) {
            int colb = wn * 16 + nf * 8 + t4 * 2;
            #pragma unroll
            for (int half = 0; half < 2; half++) {
                int row = wm * 32 + mf * 16 + g + half * 8;
                size_t off = (size_t)(rb + row) * HH + h * 64 + colb;
                *(float2*)&o[off] = make_float2(oacc[mf][nf][half * 2 + 0],
                                                oacc[mf][nf][half * 2 + 1]);
            }
        }
}

// ---------------- batched [64,64] Gram over 512 (tf32 MMA) ----------------
struct DJob { const float* A; const float* B; float* C; };
struct DParams { DJob jobs[6]; int n; };
__global__ __launch_bounds__(256) void gram_kernel(DParams P) {
    DJob job = P.jobs[blockIdx.x];
    int b = blockIdx.y;
    __shared__ float As[64][36];
    __shared__ float Bs[32][72];
    int tid = threadIdx.x;
    int lane = tid & 31, wid = tid >> 5;
    int wm = wid >> 2, wn = wid & 3;
    int g = lane >> 2, t4 = lane & 3;

    float acc[2][2][4];
    #pragma unroll
    for (int mf = 0; mf < 2; mf++)
        #pragma unroll
        for (int nf = 0; nf < 2; nf++)
            #pragma unroll
            for (int r = 0; r < 4; r++) acc[mf][nf][r] = 0.f;

    for (int kc = 0; kc < 16; kc++) {
        // A chunk [64 rows][32 k] direct
        #pragma unroll
        for (int r = 0; r < 2; r++) {
            int idx = tid + r * 256;           // 512 float4
            int i = idx >> 3, cg = idx & 7;
            float4 f = *(const float4*)&job.A[(size_t)(b * 64 + i) * HH + kc * 32 + cg * 4];
            *(float4*)&As[i][cg * 4] = f;
        }
        // B chunk transposed: Bs[k][m] = B[m][k]
        #pragma unroll
        for (int r = 0; r < 2; r++) {
            int idx = tid + r * 256;
            int m = idx & 63, cg = idx >> 6;   // cg 0..7
            float4 f = *(const float4*)&job.B[(size_t)(b * 64 + m) * HH + kc * 32 + cg * 4];
            Bs[cg * 4 + 0][m] = f.x;
            Bs[cg * 4 + 1][m] = f.y;
            Bs[cg * 4 + 2][m] = f.z;
            Bs[cg * 4 + 3][m] = f.w;
        }
        __syncthreads();
        #pragma unroll
        for (int ks = 0; ks < 4; ks++) {
            uint32_t a[2][4], bb[2][2];
            #pragma unroll
            for (int mf = 0; mf < 2; mf++) {
                int r0 = wm * 32 + mf * 16;
                a[mf][0] = f2tf32(As[r0 + g][ks * 8 + t4]);
                a[mf][1] = f2tf32(As[r0 + 8 + g][ks * 8 + t4]);
                a[mf][2] = f2tf32(As[r0 + g][ks * 8 + t4 + 4]);
                a[mf][3] = f2tf32(As[r0 + 8 + g][ks * 8 + t4 + 4]);
            }
            #pragma unroll
            for (int nf = 0; nf < 2; nf++) {
                int c0 = wn * 16 + nf * 8;
                bb[nf][0] = f2tf32(Bs[ks * 8 + t4][c0 + g]);
                bb[nf][1] = f2tf32(Bs[ks * 8 + t4 + 4][c0 + g]);
            }
            #pragma unroll
            for (int mf = 0; mf < 2; mf++)
                #pragma unroll
                for (int nf = 0; nf < 2; nf++)
                    mma_tf32(acc[mf][nf], a[mf], bb[nf]);
        }
        __syncthreads();
    }
    float* out = job.C + (size_t)b * 4096;
    #pragma unroll
    for (int mf = 0; mf < 2; mf++)
        #pragma unroll
        for (int nf = 0; nf < 2; nf++) {
            int colb = wn * 16 + nf * 8 + t4 * 2;
            #pragma unroll
            for (int half = 0; half < 2; half++) {
                int row = wm * 32 + mf * 16 + g + half * 8;
                *(float2*)&out[row * 64 + colb] = make_float2(acc[mf][nf][half * 2 + 0],
                                                              acc[mf][nf][half * 2 + 1]);
            }
        }
}

// ---------------- psidot ----------------
struct PJob { const float* A; float* C; int rows; };
struct PParams { PJob jobs[5]; int n; };
__global__ void psidot_kernel(PParams P, const float* __restrict__ Psi) {
    PJob job = P.jobs[blockIdx.x];
    int row = blockIdx.y;
    if (row >= job.rows) return;
    int t = threadIdx.x; // 256
    int w = t >> 5, lane = t & 31;
    float s = 0.f;
    #pragma unroll
    for (int u = 0; u < 16; u++) {
        int d = lane + u * 32;
        s += job.A[(size_t)row * HH + d] * Psi[w * HH + d];
    }
    s = warpReduceSum(s);
    if (lane == 0) job.C[row * 8 + w] = s;
}

// ---------------- edge coefficient update ----------------
__global__ void edge_kernel(const int* __restrict__ adj,
                            const float* __restrict__ PsiGram,
                            const float* __restrict__ PV,
                            const float* __restrict__ PX,
                            const float* __restrict__ G,
                            const float* __restrict__ VX,
                            float* __restrict__ p0,
                            float* __restrict__ pi,
                            float* __restrict__ pj,
                            int T) {
    int bij = blockIdx.x * blockDim.x + threadIdx.x; // 32768
    int b = bij >> 12;
    int ij = bij & 4095;
    int i = ij >> 6, j = ij & 63;
    int e = adj[bij];
    int ni = b * 64 + i, nj = b * 64 + j;

    float P0 = p0[bij];
    float s = P0 * P0 * PsiGram[e * 8 + e];
    float a0 = P0 * PX[ni * 8 + e];
    float a1 = P0 * PX[nj * 8 + e];

    float ci[3], cj[3];
    for (int t = 0; t < T; t++) { ci[t] = pi[t * NE + bij]; cj[t] = pj[t * NE + bij]; }

    for (int t = 0; t < T; t++) {
        s += 2.f * P0 * (ci[t] * PV[t * (ROWS * 8) + ni * 8 + e] +
                         cj[t] * PV[t * (ROWS * 8) + nj * 8 + e]);
        const float* vx = VX + (size_t)t * NE + (size_t)b * 4096;
        a0 += ci[t] * vx[i * 64 + i] + cj[t] * vx[j * 64 + i];
        a1 += ci[t] * vx[i * 64 + j] + cj[t] * vx[j * 64 + j];
        for (int ss2 = 0; ss2 < T; ss2++) {
            const float* g = G + (size_t)(ss2 * 3 + t) * NE + (size_t)b * 4096;
            s += ci[ss2] * ci[t] * g[i * 64 + i]
               + cj[ss2] * cj[t] * g[j * 64 + j]
               + 2.f * ci[ss2] * cj[t] * g[i * 64 + j];
        }
    }

    float u0 = s * INV_SCALE, u1 = a0 * INV_SCALE, u2 = a1 * INV_SCALE;
    float mm = fmaxf(u0, fmaxf(u1, u2));
    float q0 = expf(u0 - mm), q1 = expf(u1 - mm), q2 = expf(u2 - mm);
    float inv = 1.f / (q0 + q1 + q2);
    float w0 = q0 * inv;

    p0[bij] = w0 * P0;
    for (int t = 0; t < T; t++) {
        pi[t * NE + bij] = w0 * ci[t];
        pj[t * NE + bij] = w0 * cj[t];
    }
    pi[T * NE + bij] = q1 * inv;
    pj[T * NE + bij] = q2 * inv;
}

// ---------------- head ----------------
__global__ __launch_bounds__(512) void head_kernel(const float* __restrict__ x,
                                                   const float* __restrict__ Wout,
                                                   const float* __restrict__ Wpred,
                                                   const float* __restrict__ bpred,
                                                   float* __restrict__ out) {
    int b = blockIdx.x;
    int t = threadIdx.x; // 512
    __shared__ float xb[HH];
    __shared__ float cvec[HH];
    __shared__ float r0[16], r1[16];
    xb[t] = x[(size_t)(b * NN) * HH + t];
    __syncthreads();
    float s = 0.f;
    #pragma unroll 8
    for (int h2 = 0; h2 < HH; h2++) s += xb[h2] * Wout[(size_t)h2 * HH + t];
    cvec[t] = tanhf(s);
    __syncthreads();
    float pr0 = cvec[t] * Wpred[t * 2 + 0];
    float pr1 = cvec[t] * Wpred[t * 2 + 1];
    pr0 = warpReduceSum(pr0);
    pr1 = warpReduceSum(pr1);
    int lane = t & 31, w = t >> 5;
    if (lane == 0) { r0[w] = pr0; r1[w] = pr1; }
    __syncthreads();
    if (t == 0) {
        float l0 = bpred[0], l1 = bpred[1];
        #pragma unroll
        for (int q2 = 0; q2 < 16; q2++) { l0 += r0[q2]; l1 += r1[q2]; }
        float m = fmaxf(l0, l1);
        float e0 = expf(l0 - m), e1 = expf(l1 - m);
        float inv = 1.f / (e0 + e1);
        out[b * 2 + 0] = e0 * inv;
        out[b * 2 + 1] = e1 * inv;
    }
}

// ---------------- orchestration ----------------
extern "C" void kernel_launch(void* const* d_in, const int* in_sizes, int n_in,
                              void* d_out, int out_size) {
    const int* input_batch = (const int*)d_in[0];
    const int* adj = (const int*)d_in[1];
    const float* atom_emb = (const float*)d_in[2];
    const float* bond_emb = (const float*)d_in[3];
    const float* Wq = (const float*)d_in[4];
    const float* Wk = (const float*)d_in[5];
    const float* Wv = (const float*)d_in[6];
    const float* Wew = (const float*)d_in[7];
    const float* Wstack = (const float*)d_in[8];
    const float* Wf1 = (const float*)d_in[9];
    const float* Wf2 = (const float*)d_in[10];
    const float* Wout = (const float*)d_in[11];
    const float* Wpred = (const float*)d_in[12];
    const float* bpred = (const float*)d_in[13];
    float* out = (float*)d_out;

    float *x, *xn, *q, *k, *v, *o, *resid, *h1, *ff, *part, *Va, *Vb, *PsiA, *PsiB;
    float *p0, *pi, *pj, *PV, *PX, *PsiGram, *G, *VX;
    cudaGetSymbolAddress((void**)&x, g_x);
    cudaGetSymbolAddress((void**)&xn, g_xn);
    cudaGetSymbolAddress((void**)&q, g_q);
    cudaGetSymbolAddress((void**)&k, g_k);
    cudaGetSymbolAddress((void**)&v, g_v);
    cudaGetSymbolAddress((void**)&o, g_o);
    cudaGetSymbolAddress((void**)&resid, g_resid);
    cudaGetSymbolAddress((void**)&h1, g_h1);
    cudaGetSymbolAddress((void**)&ff, g_ff);
    cudaGetSymbolAddress((void**)&part, g_part);
    cudaGetSymbolAddress((void**)&Va, g_Va);
    cudaGetSymbolAddress((void**)&Vb, g_Vb);
    cudaGetSymbolAddress((void**)&PsiA, g_PsiA);
    cudaGetSymbolAddress((void**)&PsiB, g_PsiB);
    cudaGetSymbolAddress((void**)&p0, g_p0);
    cudaGetSymbolAddress((void**)&pi, g_pi);
    cudaGetSymbolAddress((void**)&pj, g_pj);
    cudaGetSymbolAddress((void**)&PV, g_PV);
    cudaGetSymbolAddress((void**)&PX, g_PX);
    cudaGetSymbolAddress((void**)&PsiGram, g_PsiGram);
    cudaGetSymbolAddress((void**)&G, g_G);
    cudaGetSymbolAddress((void**)&VX, g_VX);

    float* P0b = part;
    float* P1b = part + (size_t)ROWS * HH;
    float* P2b = part + (size_t)2 * ROWS * HH;
    float* P3b = part + (size_t)3 * ROWS * HH;

    init_kernel<<<ROWS * HH / 256, 256>>>(input_batch, atom_emb, bond_emb, x, PsiA, p0);
    ln_kernel<<<ROWS, 256>>>(x, xn);

    float* VbufA[3] = {Va, Va + ROWS * HH, Va + 2 * ROWS * HH};
    float* VbufB[3] = {Vb, Vb + ROWS * HH, Vb + 2 * ROWS * HH};
    float* prevDst[3] = {nullptr, nullptr, nullptr};

    for (int l = 0; l < NLAYERS; l++) {
        const float* Wq_l = Wq + (size_t)l * HH * HH;
        const float* Wk_l = Wk + (size_t)l * HH * HH;
        const float* Wv_l = Wv + (size_t)l * HH * HH;
        const float* Wew_l = Wew + (size_t)l * HH * HH;
        const float* Wst_l = Wstack + (size_t)l * HH * HH;
        const float* Wf1_l = Wf1 + (size_t)l * HH * FFD;
        const float* Wf2_l = Wf2 + (size_t)l * FFD * HH;

        int T = l;
        float** dst = (l & 1) ? VbufA : VbufB;
        const float* src[3];
        for (int t = 0; t < T - 1; t++) src[t] = prevDst[t];
        if (T > 0) src[T - 1] = x;
        float* psiSrc = (l & 1) ? PsiB : PsiA;
        float* psiDst = (l & 1) ? PsiA : PsiB;

        // 1) fused GEMMs: q,k,v + V'_t + Psi'
        {
            GParams P;
            int nb = 0, blk = 0;
            auto add = [&](const float* A, const float* B2, float* C2, int M, int N2, int K2,
                           int mode) {
                P.jobs[nb] = {A, B2, nullptr, C2, M, N2, K2, mode, blk, 0, K2};
                blk += (M / 64) * (N2 / 64);
                nb++;
            };
            add(xn, Wq_l, q, ROWS, HH, HH, 0);
            add(xn, Wk_l, k, ROWS, HH, HH, 0);
            add(xn, Wv_l, v, ROWS, HH, HH, 0);
            for (int t = 0; t < T; t++) add(src[t], Wew_l, dst[t], ROWS, HH, HH, 0);
            add(psiSrc, Wew_l, psiDst, 64, HH, HH, 0);
            P.nJobs = nb;
            gemm_tc_kernel<<<blk, 256>>>(P);
        }

        // 2) fused attention
        attn_fused_kernel<<<BB * NHEADS, 256>>>(q, k, v,
                                                T > 0 ? dst[0] : nullptr,
                                                T > 1 ? dst[1] : nullptr,
                                                T > 2 ? dst[2] : nullptr,
                                                psiDst, adj, p0, pi, pj, T, o);

        // 3) stack GEMM, split-K x2 -> partials
        {
            GParams P;
            P.jobs[0] = {o, Wst_l, nullptr, P0b, ROWS, HH, HH, 0, 0, 0, 256};
            P.jobs[1] = {o, Wst_l, nullptr, P1b, ROWS, HH, HH, 0, 64, 256, 256};
            P.nJobs = 2;
            gemm_tc_kernel<<<128, 256>>>(P);
        }
        // 4) resid = P0+P1+xn ; h1 = LN(resid)
        ln_combine_kernel<<<ROWS, 256>>>(P0b, P1b, P2b, P3b, xn, resid, h1, 2);

        // 5) FF1 (relu)
        {
            GParams P;
            P.jobs[0] = {h1, Wf1_l, nullptr, ff, ROWS, FFD, HH, 2, 0, 0, HH};
            P.nJobs = 1;
            gemm_tc_kernel<<<(ROWS / 64) * (FFD / 64), 256>>>(P);
        }
        // 6) FF2 split-K x4 -> partials
        {
            GParams P;
            for (int sK = 0; sK < 4; sK++)
                P.jobs[sK] = {ff, Wf2_l, nullptr, part + (size_t)sK * ROWS * HH,
                              ROWS, HH, FFD, 0, sK * 64, sK * 512, 512};
            P.nJobs = 4;
            gemm_tc_kernel<<<256, 256>>>(P);
        }
        // 7) x = sum(P) + resid ; xn = LN(x)  (xn feeds next layer)
        ln_combine_kernel<<<ROWS, 256>>>(P0b, P1b, P2b, P3b, resid, x, xn, 4);

        if (l < NLAYERS - 1) {
            // 8) Gram matrices G[s,t] and VX[t]
            int nj = 0;
            DParams DP;
            for (int s = 0; s < T; s++)
                for (int t = 0; t < T; t++)
                    DP.jobs[nj++] = {dst[s], dst[t], G + (size_t)(s * 3 + t) * NE};
            for (int t = 0; t < T; t++)
                DP.jobs[nj++] = {dst[t], x, VX + (size_t)t * NE};
            DP.n = nj;
            if (nj > 0) {
                dim3 g(nj, BB);
                gram_kernel<<<g, 256>>>(DP);
            }

            // 9) psidot: PV_t, PX, PsiGram
            {
                PParams PP2;
                int np = 0;
                for (int t = 0; t < T; t++) PP2.jobs[np++] = {dst[t], PV + t * (ROWS * 8), ROWS};
                PP2.jobs[np++] = {x, PX, ROWS};
                PP2.jobs[np++] = {psiDst, PsiGram, 32};
                PP2.n = np;
                dim3 g(np, ROWS);
                psidot_kernel<<<g, 256>>>(PP2, psiDst);
            }

            // 10) edge coefficient update
            edge_kernel<<<NE / 256, 256>>>(adj, PsiGram, PV, PX, G, VX, p0, pi, pj, T);
        }

        prevDst[0] = dst[0]; prevDst[1] = dst[1]; prevDst[2] = dst[2];
    }

    head_kernel<<<BB, 512>>>(x, Wout, Wpred, bpred, out);
}